// round 13
// baseline (speedup 1.0000x reference)
#include <cuda_runtime.h>
#include <cuda_fp16.h>
#include <math.h>
#include <stdint.h>

// Problem constants
#define B_    256
#define N_    207
#define D_    256
#define DIN_  64
#define CXG_  320
#define KC_   1280
#define NB_   52992
#define QKVLD 768
#define SCLD  208
#define ZROW  81920
#define ZK    ((size_t)NB_ * CXG_)

// ---------------- scratch ----------------
__device__ float  g_s   [(size_t)NB_ * D_];
__device__ __half g_sh  [(size_t)NB_ * D_];
__device__ __half g_qkvh[(size_t)NB_ * QKVLD];
__device__ float  g_sc  [(size_t)B_ * N_ * SCLD + 256];
__device__ __half g_sch [(size_t)B_ * N_ * SCLD + 256];
__device__ __half g_adjh[(size_t)N_ * SCLD];
__device__ __half g_oh  [(size_t)NB_ * D_];
__device__ float  g_f1  [(size_t)NB_ * D_];
__device__ float  g_s2  [(size_t)NB_ * D_];
__device__ __half g_s2h [(size_t)NB_ * D_];
__device__ __half g_poh [(size_t)NB_ * D_];
__device__ float  g_hn  [(size_t)NB_ * D_];
__device__ __half g_zh  [4 * ZK];
__device__ float  g_guc [(size_t)NB_ * 512];
__device__ __half g_wuch[(size_t)512 * KC_];
__device__ float  g_buc [512];
__device__ __half g_wqh [(size_t)QKVLD * D_];
__device__ __half g_woh [(size_t)D_ * D_];
__device__ __half g_w1h [(size_t)D_ * D_];
__device__ __half g_w2h [(size_t)D_ * D_];

// ---------------- helpers ----------------
__device__ __forceinline__ void cpa16(void* dst, const void* src, int srcbytes) {
    unsigned d = (unsigned)__cvta_generic_to_shared(dst);
    asm volatile("cp.async.cg.shared.global [%0], [%1], 16, %2;\n"
                 :: "r"(d), "l"(src), "r"(srcbytes));
}
__device__ __forceinline__ void cp_commit() {
    asm volatile("cp.async.commit_group;\n" ::: "memory");
}
template <int NGRP>
__device__ __forceinline__ void cp_wait() {
    asm volatile("cp.async.wait_group %0;\n" :: "n"(NGRP) : "memory");
}

__device__ __forceinline__ void mma_f16(float* c, const unsigned* a, const unsigned* b) {
    asm volatile(
        "mma.sync.aligned.m16n8k16.row.col.f32.f16.f16.f32 "
        "{%0,%1,%2,%3}, {%4,%5,%6,%7}, {%8,%9}, {%0,%1,%2,%3};\n"
        : "+f"(c[0]), "+f"(c[1]), "+f"(c[2]), "+f"(c[3])
        : "r"(a[0]), "r"(a[1]), "r"(a[2]), "r"(a[3]), "r"(b[0]), "r"(b[1]));
}

#define LDSM_X4(r0, r1, r2, r3, a) \
    asm volatile("ldmatrix.sync.aligned.m8n8.x4.shared.b16 {%0,%1,%2,%3}, [%4];" \
                 : "=r"(r0), "=r"(r1), "=r"(r2), "=r"(r3) : "r"(a))
#define LDSM_X4_T(r0, r1, r2, r3, a) \
    asm volatile("ldmatrix.sync.aligned.m8n8.x4.trans.shared.b16 {%0,%1,%2,%3}, [%4];" \
                 : "=r"(r0), "=r"(r1), "=r"(r2), "=r"(r3) : "r"(a))

// ---------------- FP16 tensor-core GEMM ----------------
// BM=128, BN=256, BK=64 halfs, 8 warps (256 thr), warp tile 64x64, m16n8k16.
// 4-stage cp.async (prefetch distance 2, SINGLE barrier per chunk) +
// register-level fragment double-buffering across k16 steps.
#define AS_H   (128 * 72)
#define BS_H   (256 * 72)      // >= 64*264
#define STG_H  (AS_H + BS_H)
#define NST    4

__device__ __forceinline__ void load_chunk_h(
    __half* As, __half* Bs, const __half* Ab, const __half* Bb,
    int i0, int j0, int M, int Nc, int K, int lda, int ldb,
    int k0, int tid, int transB)
{
#pragma unroll
    for (int l = 0; l < 4; ++l) {
        int e = tid + l * 256;
        int row = e >> 3, q = e & 7;
        int gr = i0 + row; if (gr > M - 1) gr = M - 1;
        int gk = k0 + q * 8;
        int rem = K - gk;
        int bytes = rem >= 8 ? 16 : (rem > 0 ? rem * 2 : 0);
        cpa16(As + row * 72 + q * 8, Ab + (size_t)gr * lda + (bytes ? gk : 0), bytes);
    }
    if (transB) {
#pragma unroll
        for (int l = 0; l < 8; ++l) {
            int e = tid + l * 256;
            int row = e >> 3, q = e & 7;
            int gr = j0 + row; if (gr > Nc - 1) gr = Nc - 1;
            int gk = k0 + q * 8;
            int rem = K - gk;
            int bytes = rem >= 8 ? 16 : (rem > 0 ? rem * 2 : 0);
            cpa16(Bs + row * 72 + q * 8, Bb + (size_t)gr * ldb + (bytes ? gk : 0), bytes);
        }
    } else {
#pragma unroll
        for (int l = 0; l < 8; ++l) {
            int e = tid + l * 256;
            int kk = e >> 5;
            int nq = (e & 31) * 8;
            int gk = k0 + kk;
            int bytes = (gk < K) ? 16 : 0;
            cpa16(Bs + kk * 264 + nq, Bb + (size_t)(bytes ? gk : 0) * ldb + j0 + nq, bytes);
        }
    }
}

__global__ __launch_bounds__(256, 1) void hgemm(
    const __half* __restrict__ A, const __half* __restrict__ Bm,
    const float* __restrict__ bias, void* __restrict__ Cp,
    int M, int Nc, int K, int lda, int ldb, int ldc,
    long long sA, long long sB, long long sC,
    float alpha, int transB, int relu, int outHalf,
    int aksub, long long akstr)
{
    extern __shared__ __half smh[];
    const uint32_t sbase = (uint32_t)__cvta_generic_to_shared(smh);

    const __half* Ab = A  + (size_t)blockIdx.z * sA;
    const __half* Bb = Bm + (size_t)blockIdx.z * sB;

    const int tid  = threadIdx.x;
    const int lane = tid & 31;
    const int wid  = tid >> 5;
    const int wr   = (wid & 1) * 64;
    const int wc   = (wid >> 1) * 64;
    const int g    = lane >> 2;
    const int t    = lane & 3;

    const int i0 = blockIdx.y * 128;
    const int j0 = blockIdx.x * 256;

    float acc[4][8][4];
#pragma unroll
    for (int mi = 0; mi < 4; ++mi)
#pragma unroll
        for (int ni = 0; ni < 8; ++ni)
#pragma unroll
            for (int q = 0; q < 4; ++q) acc[mi][ni][q] = 0.f;

    const int nk = (K + 63) / 64;

    // prologue: prefetch chunks 0,1 into stages 0,1
#pragma unroll
    for (int s = 0; s < 2; ++s) {
        if (s < nk) {
            const __half* AbC = Ab + (aksub ? (long long)((s * 64) / aksub) * akstr : 0);
            load_chunk_h(smh + s * STG_H, smh + s * STG_H + AS_H, AbC, Bb,
                         i0, j0, M, Nc, K, lda, ldb, s * 64, tid, transB);
        }
        cp_commit();
    }

    const int a_row = (lane & 15);
    const int a_ko  = 8 * (lane >> 4);
    const int bt_row = (lane & 7) + 8 * ((lane >> 4) & 1);
    const int bt_ko  = 8 * ((lane >> 3) & 1);
    const int bn_row = (lane & 7) + 8 * ((lane >> 3) & 1);
    const int bn_co  = 8 * (lane >> 4);

    // fragment loader for one k16 step into buffer slot `bu`
#define LOADFRAG(bu, aoff, boff, kb) do {                                        \
        _Pragma("unroll")                                                        \
        for (int mi = 0; mi < 4; ++mi) {                                         \
            uint32_t ad = (aoff) + (uint32_t)((wr + mi * 16 + a_row) * 72 + (kb) + a_ko) * 2; \
            LDSM_X4(af[bu][mi][0], af[bu][mi][1], af[bu][mi][2], af[bu][mi][3], ad); \
        }                                                                        \
        if (transB) {                                                            \
            _Pragma("unroll")                                                    \
            for (int np = 0; np < 4; ++np) {                                     \
                int cc0 = wc + np * 16;                                          \
                uint32_t bd = (boff) + (uint32_t)((cc0 + bt_row) * 72 + (kb) + bt_ko) * 2; \
                LDSM_X4(bf[bu][2 * np][0], bf[bu][2 * np][1],                    \
                        bf[bu][2 * np + 1][0], bf[bu][2 * np + 1][1], bd);       \
            }                                                                    \
        } else {                                                                 \
            _Pragma("unroll")                                                    \
            for (int np = 0; np < 4; ++np) {                                     \
                int cc0 = wc + np * 16;                                          \
                uint32_t bd = (boff) + (uint32_t)(((kb) + bn_row) * 264 + cc0 + bn_co) * 2; \
                LDSM_X4_T(bf[bu][2 * np][0], bf[bu][2 * np][1],                  \
                          bf[bu][2 * np + 1][0], bf[bu][2 * np + 1][1], bd);     \
            }                                                                    \
        }                                                                        \
    } while (0)

    unsigned af[2][4][4];
    unsigned bf[2][8][2];

    for (int c = 0; c < nk; ++c) {
        int pf = c + 2;
        if (pf < nk) {
            int st = pf % NST;
            const __half* AbC = Ab + (aksub ? (long long)((pf * 64) / aksub) * akstr : 0);
            load_chunk_h(smh + st * STG_H, smh + st * STG_H + AS_H, AbC, Bb,
                         i0, j0, M, Nc, K, lda, ldb, pf * 64, tid, transB);
        }
        cp_commit();
        cp_wait<2>();
        __syncthreads();     // single barrier per chunk (4 stages, distance 2)

        const uint32_t aoff = sbase + (uint32_t)((c % NST) * STG_H) * 2;
        const uint32_t boff = aoff + AS_H * 2;

        LOADFRAG(0, aoff, boff, 0);
#pragma unroll
        for (int k16 = 0; k16 < 4; ++k16) {
            const int cur = k16 & 1, nxt = cur ^ 1;
            if (k16 < 3) {
                const int kb2 = (k16 + 1) * 16;
                LOADFRAG(nxt, aoff, boff, kb2);
            }
#pragma unroll
            for (int mi = 0; mi < 4; ++mi)
#pragma unroll
                for (int ni = 0; ni < 8; ++ni)
                    mma_f16(acc[mi][ni], af[cur][mi], bf[cur][ni]);
        }
    }
    cp_wait<0>();
#undef LOADFRAG

    // epilogue
    float* Cf = (float*)Cp + (size_t)blockIdx.z * sC;
    __half* Ch = (__half*)Cp + (size_t)blockIdx.z * sC;
#pragma unroll
    for (int mi = 0; mi < 4; ++mi) {
        int r0 = i0 + wr + mi * 16 + g;
#pragma unroll
        for (int ni = 0; ni < 8; ++ni) {
            int c0 = j0 + wc + ni * 8 + 2 * t;
            float b0v = 0.f, b1v = 0.f;
            if (bias && c0 < Nc) { b0v = bias[c0]; b1v = (c0 + 1 < Nc) ? bias[c0 + 1] : 0.f; }
            float v00 = alpha * acc[mi][ni][0] + b0v;
            float v01 = alpha * acc[mi][ni][1] + b1v;
            float v10 = alpha * acc[mi][ni][2] + b0v;
            float v11 = alpha * acc[mi][ni][3] + b1v;
            if (relu) {
                v00 = fmaxf(v00, 0.f); v01 = fmaxf(v01, 0.f);
                v10 = fmaxf(v10, 0.f); v11 = fmaxf(v11, 0.f);
            }
            if (outHalf) {
                if (r0 < M && c0 < Nc)
                    *(__half2*)&Ch[(size_t)r0 * ldc + c0] = __floats2half2_rn(v00, v01);
                if (r0 + 8 < M && c0 < Nc)
                    *(__half2*)&Ch[(size_t)(r0 + 8) * ldc + c0] = __floats2half2_rn(v10, v11);
            } else {
                if (r0 < M) {
                    if (c0 < Nc)     Cf[(size_t)r0 * ldc + c0]     = v00;
                    if (c0 + 1 < Nc) Cf[(size_t)r0 * ldc + c0 + 1] = v01;
                }
                if (r0 + 8 < M) {
                    if (c0 < Nc)     Cf[(size_t)(r0 + 8) * ldc + c0]     = v10;
                    if (c0 + 1 < Nc) Cf[(size_t)(r0 + 8) * ldc + c0 + 1] = v11;
                }
            }
        }
    }
}

// ---------------- elementwise kernels ----------------

// merged prep
#define PR0 (QKVLD * D_)
#define PR1 (PR0 + D_ * D_)
#define PR2 (PR1 + D_ * D_)
#define PR3 (PR2 + D_ * D_)
#define PR4 (PR3 + 512 * KC_)
#define PR5 (PR4 + 512)
#define PR6 (PR5 + N_ * SCLD)
__global__ void prep_all(const float* __restrict__ wq, const float* __restrict__ wo,
                         const float* __restrict__ w1, const float* __restrict__ w2,
                         const float* __restrict__ Wu, const float* __restrict__ Wc,
                         const float* __restrict__ bu, const float* __restrict__ bc,
                         const float* __restrict__ adj) {
    int i = blockIdx.x * 256 + threadIdx.x;
    if (i < PR0) {
        g_wqh[i] = __float2half(wq[i]);
    } else if (i < PR1) {
        int j = i - PR0; g_woh[j] = __float2half(wo[j]);
    } else if (i < PR2) {
        int j = i - PR1; g_w1h[j] = __float2half(w1[j]);
    } else if (i < PR3) {
        int j = i - PR2; g_w2h[j] = __float2half(w2[j]);
    } else if (i < PR4) {
        int j = i - PR3;
        int row = j / KC_, k = j % KC_;
        float v = (row < 256) ? Wu[(size_t)row * KC_ + k] : Wc[(size_t)(row - 256) * KC_ + k];
        g_wuch[j] = __float2half(v);
    } else if (i < PR5) {
        int j = i - PR4;
        g_buc[j] = (j < 256) ? bu[j] : bc[j - 256];
    } else if (i < PR6) {
        int j = i - PR5;
        int r = j / SCLD, c = j % SCLD;
        g_adjh[j] = __float2half((c < N_) ? adj[(size_t)r * N_ + c] : 0.f);
    }
}

__global__ void trans_h(const float* __restrict__ h, const float* __restrict__ embed,
                        const float* __restrict__ mlt) {
    int b = blockIdx.z;
    int n0 = blockIdx.x * 32, c0 = blockIdx.y * 32;
    __shared__ float tile[32][33];
    int tx = threadIdx.x, ty = threadIdx.y;
#pragma unroll
    for (int l = 0; l < 4; ++l) {
        int c = c0 + ty + l * 8;
        int n = n0 + tx;
        tile[ty + l * 8][tx] = (n < N_) ? h[((size_t)b * D_ + c) * N_ + n] : 0.f;
    }
    __syncthreads();
#pragma unroll
    for (int l = 0; l < 4; ++l) {
        int n = n0 + ty + l * 8;
        if (n < N_) {
            int c = c0 + tx;
            float m = mlt[(size_t)b * N_ + n];
            float v = tile[tx][ty + l * 8] + embed[(size_t)n * D_ + c] * m;
            size_t idx = ((size_t)b * N_ + n) * D_ + c;
            g_s[idx] = v;
            g_sh[idx] = __float2half(v);
        }
    }
}

__global__ void trans_x(const float* __restrict__ x) {
    int b = blockIdx.z;
    int n0 = blockIdx.x * 32, c0 = blockIdx.y * 32;
    __shared__ float tile[32][33];
    int tx = threadIdx.x, ty = threadIdx.y;
#pragma unroll
    for (int l = 0; l < 4; ++l) {
        int c = c0 + ty + l * 8;
        int n = n0 + tx;
        tile[ty + l * 8][tx] = (n < N_) ? x[((size_t)b * DIN_ + c) * N_ + n] : 0.f;
    }
    __syncthreads();
#pragma unroll
    for (int l = 0; l < 4; ++l) {
        int n = n0 + ty + l * 8;
        if (n < N_)
            g_zh[((size_t)n * B_ + b) * CXG_ + c0 + tx] = __float2half(tile[tx][ty + l * 8]);
    }
}

__global__ void softmax_rows(const float* __restrict__ sc, __half* __restrict__ sch) {
    int row = blockIdx.x * 8 + threadIdx.y;
    const float* p = sc + (size_t)row * SCLD;
    __half* ph = sch + (size_t)row * SCLD;
    int lane = threadIdx.x;
    float mx = -1e30f;
    for (int j = lane; j < N_; j += 32) mx = fmaxf(mx, p[j]);
#pragma unroll
    for (int o = 16; o > 0; o >>= 1) mx = fmaxf(mx, __shfl_xor_sync(0xffffffffu, mx, o));
    float sum = 0.f;
    float ev[7];
    int cnt = 0;
    for (int j = lane; j < N_; j += 32) { float e = expf(p[j] - mx); ev[cnt++] = e; sum += e; }
#pragma unroll
    for (int o = 16; o > 0; o >>= 1) sum += __shfl_xor_sync(0xffffffffu, sum, o);
    float inv = 1.f / sum;
    cnt = 0;
    for (int j = lane; j < N_; j += 32) ph[j] = __float2half(ev[cnt++] * inv);
}

__device__ __forceinline__ float2 ln_stats(float v, int c, float* red2) {
    float s = v, q = v * v;
#pragma unroll
    for (int o = 16; o > 0; o >>= 1) {
        s += __shfl_xor_sync(0xffffffffu, s, o);
        q += __shfl_xor_sync(0xffffffffu, q, o);
    }
    if ((c & 31) == 0) { red2[(c >> 5) * 2] = s; red2[(c >> 5) * 2 + 1] = q; }
    __syncthreads();
    float ts = 0.f, tq = 0.f;
#pragma unroll
    for (int w = 0; w < 8; ++w) { ts += red2[w * 2]; tq += red2[w * 2 + 1]; }
    float mu = ts * (1.f / 256.f);
    float var = tq * (1.f / 256.f) - mu * mu;
    return make_float2(mu, rsqrtf(var + 1e-5f));
}

__global__ void add_ln(const float* __restrict__ a, const float* __restrict__ bsrc,
                       const float* __restrict__ w, const float* __restrict__ bb,
                       float* __restrict__ outf, __half* __restrict__ outh) {
    int r = blockIdx.x, c = threadIdx.x;
    size_t idx = (size_t)r * D_ + c;
    float v = a[idx] + bsrc[idx];
    __shared__ float red2[16];
    float2 st = ln_stats(v, c, red2);
    float o = (v - st.x) * st.y * w[c] + bb[c];
    outf[idx] = o;
    outh[idx] = __float2half(o);
}

__global__ void ln2_make_h(const float* __restrict__ a, const float* __restrict__ bsrc,
                           const float* __restrict__ w, const float* __restrict__ bb,
                           const float* __restrict__ embed, const float* __restrict__ mlt,
                           const float* __restrict__ dt, const int* __restrict__ step) {
    int r = blockIdx.x, c = threadIdx.x;
    int b = r / N_, n = r % N_;
    size_t idx = (size_t)r * D_ + c;
    float v = a[idx] + bsrc[idx];
    __shared__ float red2[16];
    float2 st = ln_stats(v, c, red2);
    float s3v = (v - st.x) * st.y * w[c] + bb[c];

    float hv = g_s[idx] - embed[(size_t)n * D_ + c] * mlt[(size_t)b * N_ + n];
    float hn;
    if (*step != 0) {
        float d = dt[b];
        hn = sqrtf(1.f - d) * hv - sqrtf(d) * tanhf(s3v);
    } else {
        hn = hv;
    }
    g_hn[idx] = hn;
    g_zh[((size_t)n * B_ + b) * CXG_ + DIN_ + c] = __float2half(hn);
}

__global__ void final_combine(float* __restrict__ outp) {
    int b = blockIdx.z;
    int o0 = blockIdx.y * 32, n0 = blockIdx.x * 32;
    __shared__ float tbuf[32][33];
    int tx = threadIdx.x, ty = threadIdx.y;
#pragma unroll
    for (int s4 = 0; s4 < 4; ++s4) {
        int nl = ty + s4 * 8;
        int n = n0 + nl;
        float val = 0.f;
        if (n < N_) {
            size_t rp = (size_t)n * B_ + b;
            float gu = g_guc[rp * 512 + o0 + tx];
            float gc = g_guc[rp * 512 + 256 + o0 + tx];
            float uu = 1.f / (1.f + expf(-gu));
            float cc = tanhf(gc);
            val = uu * g_hn[((size_t)b * N_ + n) * D_ + o0 + tx] + (1.f - uu) * cc;
        }
        tbuf[nl][tx] = val;
    }
    __syncthreads();
#pragma unroll
    for (int s4 = 0; s4 < 4; ++s4) {
        int ol = ty + s4 * 8;
        int n = n0 + tx;
        if (n < N_)
            outp[((size_t)(b * D_ + o0 + ol)) * N_ + n] = tbuf[tx][ol];
    }
}

// ---------------- launcher ----------------
extern "C" void kernel_launch(void* const* d_in, const int* in_sizes, int n_in,
                              void* d_out, int out_size) {
    const float* x          = (const float*)d_in[0];
    const float* delta_t    = (const float*)d_in[1];
    const float* h          = (const float*)d_in[2];
    const float* adj        = (const float*)d_in[3];
    const float* mlt        = (const float*)d_in[5];
    const int*   step       = (const int*)d_in[7];
    const float* embed      = (const float*)d_in[8];
    const float* in_proj_w  = (const float*)d_in[9];
    const float* in_proj_b  = (const float*)d_in[10];
    const float* out_proj_w = (const float*)d_in[11];
    const float* out_proj_b = (const float*)d_in[12];
    const float* ln1_w      = (const float*)d_in[13];
    const float* ln1_b      = (const float*)d_in[14];
    const float* ln2_w      = (const float*)d_in[15];
    const float* ln2_b      = (const float*)d_in[16];
    const float* ffn_w1     = (const float*)d_in[17];
    const float* ffn_b1     = (const float*)d_in[18];
    const float* ffn_w2     = (const float*)d_in[19];
    const float* ffn_b2     = (const float*)d_in[20];
    const float* W_u        = (const float*)d_in[21];
    const float* b_u        = (const float*)d_in[22];
    const float* W_c        = (const float*)d_in[23];
    const float* b_c        = (const float*)d_in[24];
    float* outp = (float*)d_out;

    void *vp;
    cudaGetSymbolAddress(&vp, g_s);    float*  ps   = (float*)vp;
    cudaGetSymbolAddress(&vp, g_sh);   __half* psh  = (__half*)vp;
    cudaGetSymbolAddress(&vp, g_qkvh); __half* pqh  = (__half*)vp;
    cudaGetSymbolAddress(&vp, g_sc);   float*  psc  = (float*)vp;
    cudaGetSymbolAddress(&vp, g_sch);  __half* psch = (__half*)vp;
    cudaGetSymbolAddress(&vp, g_adjh); __half* padh = (__half*)vp;
    cudaGetSymbolAddress(&vp, g_oh);   __half* poh  = (__half*)vp;
    cudaGetSymbolAddress(&vp, g_f1);   float*  pf1  = (float*)vp;
    cudaGetSymbolAddress(&vp, g_s2);   float*  ps2  = (float*)vp;
    cudaGetSymbolAddress(&vp, g_s2h);  __half* ps2h = (__half*)vp;
    cudaGetSymbolAddress(&vp, g_poh);  __half* ppoh = (__half*)vp;
    cudaGetSymbolAddress(&vp, g_zh);   __half* pzh  = (__half*)vp;
    cudaGetSymbolAddress(&vp, g_guc);  float*  pguc = (float*)vp;
    cudaGetSymbolAddress(&vp, g_wuch); __half* pwuh = (__half*)vp;
    cudaGetSymbolAddress(&vp, g_buc);  float*  pbuc = (float*)vp;
    cudaGetSymbolAddress(&vp, g_wqh);  __half* pwq  = (__half*)vp;
    cudaGetSymbolAddress(&vp, g_woh);  __half* pwo  = (__half*)vp;
    cudaGetSymbolAddress(&vp, g_w1h);  __half* pw1  = (__half*)vp;
    cudaGetSymbolAddress(&vp, g_w2h);  __half* pw2  = (__half*)vp;

    static const int SMH = NST * STG_H * 2;   // 221184 bytes
    cudaFuncSetAttribute(hgemm, cudaFuncAttributeMaxDynamicSharedMemorySize, SMH);

    // 0. merged prep
    prep_all<<<(PR6 + 255) / 256, 256>>>(in_proj_w, out_proj_w, ffn_w1, ffn_w2,
                                         W_u, W_c, b_u, b_c, adj);

    // 1. transformer input + Z0 x-part
    trans_h<<<dim3(7, 8, B_), dim3(32, 8)>>>(h, embed, mlt);
    trans_x<<<dim3(7, 2, B_), dim3(32, 8)>>>(x);

    // 2. QKV -> fp16
    hgemm<<<dim3(3, 414, 1), 256, SMH>>>(psh, pwq, in_proj_b, pqh,
        NB_, QKVLD, 256, 256, 256, QKVLD, 0, 0, 0, 1.f, 1, 0, 1, 0, 0);

    // 3. scores: per-batch Q @ K^T / 16 -> fp32
    hgemm<<<dim3(1, 2, B_), 256, SMH>>>(pqh, pqh + 256, nullptr, psc,
        N_, N_, 256, QKVLD, QKVLD, SCLD,
        (long long)N_ * QKVLD, (long long)N_ * QKVLD, (long long)N_ * SCLD,
        1.f / 16.f, 1, 0, 0, 0, 0);

    // 4. softmax -> fp16
    softmax_rows<<<NB_ / 8, dim3(32, 8)>>>(psc, psch);

    // 5. attn @ V (NN) -> fp16
    hgemm<<<dim3(1, 2, B_), 256, SMH>>>(psch, pqh + 512, nullptr, poh,
        N_, 256, N_, SCLD, QKVLD, 256,
        (long long)N_ * SCLD, (long long)N_ * QKVLD, (long long)N_ * 256,
        1.f, 0, 0, 1, 0, 0);

    // 6. out projection -> fp32
    hgemm<<<dim3(1, 414, 1), 256, SMH>>>(poh, pwo, out_proj_b, pf1,
        NB_, 256, 256, 256, 256, 256, 0, 0, 0, 1.f, 1, 0, 0, 0, 0);

    // 7. LN1
    add_ln<<<NB_, 256>>>(ps, pf1, ln1_w, ln1_b, ps2, ps2h);

    // 8. FFN
    hgemm<<<dim3(1, 414, 1), 256, SMH>>>(ps2h, pw1, ffn_b1, ppoh,
        NB_, 256, 256, 256, 256, 256, 0, 0, 0, 1.f, 1, 1, 1, 0, 0);
    hgemm<<<dim3(1, 414, 1), 256, SMH>>>(ppoh, pw2, ffn_b2, pf1,
        NB_, 256, 256, 256, 256, 256, 0, 0, 0, 1.f, 1, 0, 0, 0, 0);

    // 9+10. LN2 + h update + Z0 h-part
    ln2_make_h<<<NB_, 256>>>(ps2, pf1, ln2_w, ln2_b, embed, mlt, delta_t, step);

    // 11. diffusion: Z_k = adj @ Z_{k-1}, dense NN (207 x 81920 x 207) -> fp16
    for (int k = 1; k <= 3; ++k) {
        hgemm<<<dim3(ZROW / 256, 2, 1), 256, SMH>>>(padh,
            pzh + (size_t)(k - 1) * ZK, nullptr, pzh + (size_t)k * ZK,
            N_, ZROW, N_, SCLD, ZROW, ZROW,
            0, 0, 0, 1.f, 0, 0, 1, 0, 0);
    }

    // 12. fused gates (blocked-K z) -> fp32
    hgemm<<<dim3(2, 414, 1), 256, SMH>>>(pzh, pwuh, pbuc, pguc,
        NB_, 512, KC_, CXG_, KC_, 512, 0, 0, 0, 1.f, 1, 0, 0,
        CXG_, (long long)ZK - CXG_);

    // 13. gated combine + transpose
    final_combine<<<dim3(7, 8, B_), dim3(32, 8)>>>(outp);
}

// round 14
// speedup vs baseline: 1.0707x; 1.0707x over previous
#include <cuda_runtime.h>
#include <cuda_fp16.h>
#include <math.h>
#include <stdint.h>

// Problem constants
#define B_    256
#define N_    207
#define D_    256
#define DIN_  64
#define CXG_  320
#define KC_   1280
#define NB_   52992
#define QKVLD 768
#define SCLD  208
#define ZROW  81920
#define ZK    ((size_t)NB_ * CXG_)

// ---------------- scratch ----------------
__device__ float  g_s   [(size_t)NB_ * D_];
__device__ __half g_sh  [(size_t)NB_ * D_];
__device__ __half g_qkvh[(size_t)NB_ * QKVLD];
__device__ __half g_sch [(size_t)B_ * N_ * SCLD + 256];
__device__ __half g_adjh[(size_t)N_ * SCLD];
__device__ __half g_oh  [(size_t)NB_ * D_];
__device__ float  g_f1  [(size_t)NB_ * D_];
__device__ float  g_s2  [(size_t)NB_ * D_];
__device__ __half g_s2h [(size_t)NB_ * D_];
__device__ __half g_poh [(size_t)NB_ * D_];
__device__ float  g_hn  [(size_t)NB_ * D_];
__device__ __half g_zh  [4 * ZK];
__device__ float  g_guc [(size_t)NB_ * 512];
__device__ __half g_wuch[(size_t)512 * KC_];
__device__ float  g_buc [512];
__device__ __half g_wqh [(size_t)QKVLD * D_];
__device__ __half g_woh [(size_t)D_ * D_];
__device__ __half g_w1h [(size_t)D_ * D_];
__device__ __half g_w2h [(size_t)D_ * D_];

// ---------------- helpers ----------------
__device__ __forceinline__ void cpa16(void* dst, const void* src, int srcbytes) {
    unsigned d = (unsigned)__cvta_generic_to_shared(dst);
    asm volatile("cp.async.cg.shared.global [%0], [%1], 16, %2;\n"
                 :: "r"(d), "l"(src), "r"(srcbytes));
}
__device__ __forceinline__ void cp_commit() {
    asm volatile("cp.async.commit_group;\n" ::: "memory");
}
template <int NGRP>
__device__ __forceinline__ void cp_wait() {
    asm volatile("cp.async.wait_group %0;\n" :: "n"(NGRP) : "memory");
}

__device__ __forceinline__ void mma_f16(float* c, const unsigned* a, const unsigned* b) {
    asm volatile(
        "mma.sync.aligned.m16n8k16.row.col.f32.f16.f16.f32 "
        "{%0,%1,%2,%3}, {%4,%5,%6,%7}, {%8,%9}, {%0,%1,%2,%3};\n"
        : "+f"(c[0]), "+f"(c[1]), "+f"(c[2]), "+f"(c[3])
        : "r"(a[0]), "r"(a[1]), "r"(a[2]), "r"(a[3]), "r"(b[0]), "r"(b[1]));
}

#define LDSM_X4(r0, r1, r2, r3, a) \
    asm volatile("ldmatrix.sync.aligned.m8n8.x4.shared.b16 {%0,%1,%2,%3}, [%4];" \
                 : "=r"(r0), "=r"(r1), "=r"(r2), "=r"(r3) : "r"(a))
#define LDSM_X4_T(r0, r1, r2, r3, a) \
    asm volatile("ldmatrix.sync.aligned.m8n8.x4.trans.shared.b16 {%0,%1,%2,%3}, [%4];" \
                 : "=r"(r0), "=r"(r1), "=r"(r2), "=r"(r3) : "r"(a))

// ---------------- FP16 tensor-core GEMM ----------------
// BM=128, BN=256, BK=64 halfs, 16 warps (512 thr), warp tile 32x64, m16n8k16,
// LDSM fragments, 4-stage cp.async (prefetch dist 2), ONE barrier per chunk.
#define AS_H   (128 * 72)
#define BS_H   (256 * 72)      // >= 64*264
#define STG_H  (AS_H + BS_H)
#define NST    4

__device__ __forceinline__ void load_chunk_h(
    __half* As, __half* Bs, const __half* Ab, const __half* Bb,
    int i0, int j0, int M, int Nc, int K, int lda, int ldb,
    int k0, int tid, int transB)
{
#pragma unroll
    for (int l = 0; l < 2; ++l) {
        int e = tid + l * 512;
        int row = e >> 3, q = e & 7;
        int gr = i0 + row; if (gr > M - 1) gr = M - 1;
        int gk = k0 + q * 8;
        int rem = K - gk;
        int bytes = rem >= 8 ? 16 : (rem > 0 ? rem * 2 : 0);
        cpa16(As + row * 72 + q * 8, Ab + (size_t)gr * lda + (bytes ? gk : 0), bytes);
    }
    if (transB) {
#pragma unroll
        for (int l = 0; l < 4; ++l) {
            int e = tid + l * 512;
            int row = e >> 3, q = e & 7;
            int gr = j0 + row; if (gr > Nc - 1) gr = Nc - 1;
            int gk = k0 + q * 8;
            int rem = K - gk;
            int bytes = rem >= 8 ? 16 : (rem > 0 ? rem * 2 : 0);
            cpa16(Bs + row * 72 + q * 8, Bb + (size_t)gr * ldb + (bytes ? gk : 0), bytes);
        }
    } else {
#pragma unroll
        for (int l = 0; l < 4; ++l) {
            int e = tid + l * 512;
            int kk = e >> 5;
            int nq = (e & 31) * 8;
            int gk = k0 + kk;
            int bytes = (gk < K) ? 16 : 0;
            cpa16(Bs + kk * 264 + nq, Bb + (size_t)(bytes ? gk : 0) * ldb + j0 + nq, bytes);
        }
    }
}

__global__ __launch_bounds__(512, 1) void hgemm(
    const __half* __restrict__ A, const __half* __restrict__ Bm,
    const float* __restrict__ bias, void* __restrict__ Cp,
    int M, int Nc, int K, int lda, int ldb, int ldc,
    long long sA, long long sB, long long sC,
    float alpha, int transB, int relu, int outHalf,
    int aksub, long long akstr)
{
    extern __shared__ __half smh[];
    const uint32_t sbase = (uint32_t)__cvta_generic_to_shared(smh);

    const __half* Ab = A  + (size_t)blockIdx.z * sA;
    const __half* Bb = Bm + (size_t)blockIdx.z * sB;

    const int tid  = threadIdx.x;
    const int lane = tid & 31;
    const int wid  = tid >> 5;
    const int wr   = (wid & 3) * 32;
    const int wc   = (wid >> 2) * 64;
    const int g    = lane >> 2;
    const int t    = lane & 3;

    const int i0 = blockIdx.y * 128;
    const int j0 = blockIdx.x * 256;

    float acc[2][8][4];
#pragma unroll
    for (int mi = 0; mi < 2; ++mi)
#pragma unroll
        for (int ni = 0; ni < 8; ++ni)
#pragma unroll
            for (int q = 0; q < 4; ++q) acc[mi][ni][q] = 0.f;

    const int nk = (K + 63) / 64;

#pragma unroll
    for (int s = 0; s < 2; ++s) {
        if (s < nk) {
            const __half* AbC = Ab + (aksub ? (long long)((s * 64) / aksub) * akstr : 0);
            load_chunk_h(smh + s * STG_H, smh + s * STG_H + AS_H, AbC, Bb,
                         i0, j0, M, Nc, K, lda, ldb, s * 64, tid, transB);
        }
        cp_commit();
    }

    const int a_row = (lane & 15);
    const int a_ko  = 8 * (lane >> 4);
    const int bt_row = (lane & 7) + 8 * ((lane >> 4) & 1);
    const int bt_ko  = 8 * ((lane >> 3) & 1);
    const int bn_row = (lane & 7) + 8 * ((lane >> 3) & 1);
    const int bn_co  = 8 * (lane >> 4);

    for (int c = 0; c < nk; ++c) {
        int pf = c + 2;
        if (pf < nk) {
            int st = pf % NST;
            const __half* AbC = Ab + (aksub ? (long long)((pf * 64) / aksub) * akstr : 0);
            load_chunk_h(smh + st * STG_H, smh + st * STG_H + AS_H, AbC, Bb,
                         i0, j0, M, Nc, K, lda, ldb, pf * 64, tid, transB);
        }
        cp_commit();
        cp_wait<2>();
        __syncthreads();   // single barrier per chunk (4 stages, distance 2)

        const uint32_t aoff = sbase + (uint32_t)((c % NST) * STG_H) * 2;
        const uint32_t boff = aoff + AS_H * 2;

#pragma unroll
        for (int k16 = 0; k16 < 4; ++k16) {
            const int kb = k16 * 16;
            unsigned af[2][4];
#pragma unroll
            for (int mi = 0; mi < 2; ++mi) {
                uint32_t ad = aoff + (uint32_t)((wr + mi * 16 + a_row) * 72 + kb + a_ko) * 2;
                LDSM_X4(af[mi][0], af[mi][1], af[mi][2], af[mi][3], ad);
            }
            unsigned bf[8][2];
            if (transB) {
#pragma unroll
                for (int np = 0; np < 4; ++np) {
                    int cc0 = wc + np * 16;
                    uint32_t bd = boff + (uint32_t)((cc0 + bt_row) * 72 + kb + bt_ko) * 2;
                    LDSM_X4(bf[2 * np][0], bf[2 * np][1],
                            bf[2 * np + 1][0], bf[2 * np + 1][1], bd);
                }
            } else {
#pragma unroll
                for (int np = 0; np < 4; ++np) {
                    int cc0 = wc + np * 16;
                    uint32_t bd = boff + (uint32_t)((kb + bn_row) * 264 + cc0 + bn_co) * 2;
                    LDSM_X4_T(bf[2 * np][0], bf[2 * np][1],
                              bf[2 * np + 1][0], bf[2 * np + 1][1], bd);
                }
            }
#pragma unroll
            for (int mi = 0; mi < 2; ++mi)
#pragma unroll
                for (int ni = 0; ni < 8; ++ni)
                    mma_f16(acc[mi][ni], af[mi], bf[ni]);
        }
    }
    cp_wait<0>();

    // epilogue
    float* Cf = (float*)Cp + (size_t)blockIdx.z * sC;
    __half* Ch = (__half*)Cp + (size_t)blockIdx.z * sC;
#pragma unroll
    for (int mi = 0; mi < 2; ++mi) {
        int r0 = i0 + wr + mi * 16 + g;
#pragma unroll
        for (int ni = 0; ni < 8; ++ni) {
            int c0 = j0 + wc + ni * 8 + 2 * t;
            float b0v = 0.f, b1v = 0.f;
            if (bias && c0 < Nc) { b0v = bias[c0]; b1v = (c0 + 1 < Nc) ? bias[c0 + 1] : 0.f; }
            float v00 = alpha * acc[mi][ni][0] + b0v;
            float v01 = alpha * acc[mi][ni][1] + b1v;
            float v10 = alpha * acc[mi][ni][2] + b0v;
            float v11 = alpha * acc[mi][ni][3] + b1v;
            if (relu) {
                v00 = fmaxf(v00, 0.f); v01 = fmaxf(v01, 0.f);
                v10 = fmaxf(v10, 0.f); v11 = fmaxf(v11, 0.f);
            }
            if (outHalf) {
                if (r0 < M && c0 < Nc)
                    *(__half2*)&Ch[(size_t)r0 * ldc + c0] = __floats2half2_rn(v00, v01);
                if (r0 + 8 < M && c0 < Nc)
                    *(__half2*)&Ch[(size_t)(r0 + 8) * ldc + c0] = __floats2half2_rn(v10, v11);
            } else {
                if (r0 < M) {
                    if (c0 < Nc)     Cf[(size_t)r0 * ldc + c0]     = v00;
                    if (c0 + 1 < Nc) Cf[(size_t)r0 * ldc + c0 + 1] = v01;
                }
                if (r0 + 8 < M) {
                    if (c0 < Nc)     Cf[(size_t)(r0 + 8) * ldc + c0]     = v10;
                    if (c0 + 1 < Nc) Cf[(size_t)(r0 + 8) * ldc + c0 + 1] = v11;
                }
            }
        }
    }
}

// ---------------- elementwise kernels ----------------

// merged prep
#define PR0 (QKVLD * D_)
#define PR1 (PR0 + D_ * D_)
#define PR2 (PR1 + D_ * D_)
#define PR3 (PR2 + D_ * D_)
#define PR4 (PR3 + 512 * KC_)
#define PR5 (PR4 + 512)
#define PR6 (PR5 + N_ * SCLD)
__global__ void prep_all(const float* __restrict__ wq, const float* __restrict__ wo,
                         const float* __restrict__ w1, const float* __restrict__ w2,
                         const float* __restrict__ Wu, const float* __restrict__ Wc,
                         const float* __restrict__ bu, const float* __restrict__ bc,
                         const float* __restrict__ adj) {
    int i = blockIdx.x * 256 + threadIdx.x;
    if (i < PR0) {
        g_wqh[i] = __float2half(wq[i]);
    } else if (i < PR1) {
        int j = i - PR0; g_woh[j] = __float2half(wo[j]);
    } else if (i < PR2) {
        int j = i - PR1; g_w1h[j] = __float2half(w1[j]);
    } else if (i < PR3) {
        int j = i - PR2; g_w2h[j] = __float2half(w2[j]);
    } else if (i < PR4) {
        int j = i - PR3;
        int row = j / KC_, k = j % KC_;
        float v = (row < 256) ? Wu[(size_t)row * KC_ + k] : Wc[(size_t)(row - 256) * KC_ + k];
        g_wuch[j] = __float2half(v);
    } else if (i < PR5) {
        int j = i - PR4;
        g_buc[j] = (j < 256) ? bu[j] : bc[j - 256];
    } else if (i < PR6) {
        int j = i - PR5;
        int r = j / SCLD, c = j % SCLD;
        g_adjh[j] = __float2half((c < N_) ? adj[(size_t)r * N_ + c] : 0.f);
    }
}

// merged transpose: blockIdx.y < 8 -> h part (s), else x part (Z0 x cols)
__global__ void trans_hx(const float* __restrict__ h, const float* __restrict__ x,
                         const float* __restrict__ embed, const float* __restrict__ mlt) {
    int b = blockIdx.z;
    int n0 = blockIdx.x * 32;
    __shared__ float tile[32][33];
    int tx = threadIdx.x, ty = threadIdx.y;
    if (blockIdx.y < 8) {
        int c0 = blockIdx.y * 32;
#pragma unroll
        for (int l = 0; l < 4; ++l) {
            int c = c0 + ty + l * 8;
            int n = n0 + tx;
            tile[ty + l * 8][tx] = (n < N_) ? h[((size_t)b * D_ + c) * N_ + n] : 0.f;
        }
        __syncthreads();
#pragma unroll
        for (int l = 0; l < 4; ++l) {
            int n = n0 + ty + l * 8;
            if (n < N_) {
                int c = c0 + tx;
                float m = mlt[(size_t)b * N_ + n];
                float v = tile[tx][ty + l * 8] + embed[(size_t)n * D_ + c] * m;
                size_t idx = ((size_t)b * N_ + n) * D_ + c;
                g_s[idx] = v;
                g_sh[idx] = __float2half(v);
            }
        }
    } else {
        int c0 = (blockIdx.y - 8) * 32;
#pragma unroll
        for (int l = 0; l < 4; ++l) {
            int c = c0 + ty + l * 8;
            int n = n0 + tx;
            tile[ty + l * 8][tx] = (n < N_) ? x[((size_t)b * DIN_ + c) * N_ + n] : 0.f;
        }
        __syncthreads();
#pragma unroll
        for (int l = 0; l < 4; ++l) {
            int n = n0 + ty + l * 8;
            if (n < N_)
                g_zh[((size_t)n * B_ + b) * CXG_ + c0 + tx] = __float2half(tile[tx][ty + l * 8]);
        }
    }
}

// in-place softmax on fp16 scores (fp32 math in registers)
__global__ void softmax_rows(__half* __restrict__ sch) {
    int row = blockIdx.x * 8 + threadIdx.y;
    __half* p = sch + (size_t)row * SCLD;
    int lane = threadIdx.x;
    float ev[7];
    float mx = -1e30f;
    int cnt = 0;
    for (int j = lane; j < N_; j += 32) {
        float v = __half2float(p[j]);
        ev[cnt++] = v;
        mx = fmaxf(mx, v);
    }
#pragma unroll
    for (int o = 16; o > 0; o >>= 1) mx = fmaxf(mx, __shfl_xor_sync(0xffffffffu, mx, o));
    float sum = 0.f;
    for (int i = 0; i < cnt; ++i) { ev[i] = expf(ev[i] - mx); sum += ev[i]; }
#pragma unroll
    for (int o = 16; o > 0; o >>= 1) sum += __shfl_xor_sync(0xffffffffu, sum, o);
    float inv = 1.f / sum;
    cnt = 0;
    for (int j = lane; j < N_; j += 32) p[j] = __float2half(ev[cnt++] * inv);
}

__device__ __forceinline__ float2 ln_stats(float v, int c, float* red2) {
    float s = v, q = v * v;
#pragma unroll
    for (int o = 16; o > 0; o >>= 1) {
        s += __shfl_xor_sync(0xffffffffu, s, o);
        q += __shfl_xor_sync(0xffffffffu, q, o);
    }
    if ((c & 31) == 0) { red2[(c >> 5) * 2] = s; red2[(c >> 5) * 2 + 1] = q; }
    __syncthreads();
    float ts = 0.f, tq = 0.f;
#pragma unroll
    for (int w = 0; w < 8; ++w) { ts += red2[w * 2]; tq += red2[w * 2 + 1]; }
    float mu = ts * (1.f / 256.f);
    float var = tq * (1.f / 256.f) - mu * mu;
    return make_float2(mu, rsqrtf(var + 1e-5f));
}

__global__ void add_ln(const float* __restrict__ a, const float* __restrict__ bsrc,
                       const float* __restrict__ w, const float* __restrict__ bb,
                       float* __restrict__ outf, __half* __restrict__ outh) {
    int r = blockIdx.x, c = threadIdx.x;
    size_t idx = (size_t)r * D_ + c;
    float v = a[idx] + bsrc[idx];
    __shared__ float red2[16];
    float2 st = ln_stats(v, c, red2);
    float o = (v - st.x) * st.y * w[c] + bb[c];
    outf[idx] = o;
    outh[idx] = __float2half(o);
}

__global__ void ln2_make_h(const float* __restrict__ a, const float* __restrict__ bsrc,
                           const float* __restrict__ w, const float* __restrict__ bb,
                           const float* __restrict__ embed, const float* __restrict__ mlt,
                           const float* __restrict__ dt, const int* __restrict__ step) {
    int r = blockIdx.x, c = threadIdx.x;
    int b = r / N_, n = r % N_;
    size_t idx = (size_t)r * D_ + c;
    float v = a[idx] + bsrc[idx];
    __shared__ float red2[16];
    float2 st = ln_stats(v, c, red2);
    float s3v = (v - st.x) * st.y * w[c] + bb[c];

    float hv = g_s[idx] - embed[(size_t)n * D_ + c] * mlt[(size_t)b * N_ + n];
    float hn;
    if (*step != 0) {
        float d = dt[b];
        hn = sqrtf(1.f - d) * hv - sqrtf(d) * tanhf(s3v);
    } else {
        hn = hv;
    }
    g_hn[idx] = hn;
    g_zh[((size_t)n * B_ + b) * CXG_ + DIN_ + c] = __float2half(hn);
}

__global__ void final_combine(float* __restrict__ outp) {
    int b = blockIdx.z;
    int o0 = blockIdx.y * 32, n0 = blockIdx.x * 32;
    __shared__ float tbuf[32][33];
    int tx = threadIdx.x, ty = threadIdx.y;
#pragma unroll
    for (int s4 = 0; s4 < 4; ++s4) {
        int nl = ty + s4 * 8;
        int n = n0 + nl;
        float val = 0.f;
        if (n < N_) {
            size_t rp = (size_t)n * B_ + b;
            float gu = g_guc[rp * 512 + o0 + tx];
            float gc = g_guc[rp * 512 + 256 + o0 + tx];
            float uu = 1.f / (1.f + expf(-gu));
            float cc = tanhf(gc);
            val = uu * g_hn[((size_t)b * N_ + n) * D_ + o0 + tx] + (1.f - uu) * cc;
        }
        tbuf[nl][tx] = val;
    }
    __syncthreads();
#pragma unroll
    for (int s4 = 0; s4 < 4; ++s4) {
        int ol = ty + s4 * 8;
        int n = n0 + tx;
        if (n < N_)
            outp[((size_t)(b * D_ + o0 + ol)) * N_ + n] = tbuf[tx][ol];
    }
}

// ---------------- launcher ----------------
extern "C" void kernel_launch(void* const* d_in, const int* in_sizes, int n_in,
                              void* d_out, int out_size) {
    const float* x          = (const float*)d_in[0];
    const float* delta_t    = (const float*)d_in[1];
    const float* h          = (const float*)d_in[2];
    const float* adj        = (const float*)d_in[3];
    const float* mlt        = (const float*)d_in[5];
    const int*   step       = (const int*)d_in[7];
    const float* embed      = (const float*)d_in[8];
    const float* in_proj_w  = (const float*)d_in[9];
    const float* in_proj_b  = (const float*)d_in[10];
    const float* out_proj_w = (const float*)d_in[11];
    const float* out_proj_b = (const float*)d_in[12];
    const float* ln1_w      = (const float*)d_in[13];
    const float* ln1_b      = (const float*)d_in[14];
    const float* ln2_w      = (const float*)d_in[15];
    const float* ln2_b      = (const float*)d_in[16];
    const float* ffn_w1     = (const float*)d_in[17];
    const float* ffn_b1     = (const float*)d_in[18];
    const float* ffn_w2     = (const float*)d_in[19];
    const float* ffn_b2     = (const float*)d_in[20];
    const float* W_u        = (const float*)d_in[21];
    const float* b_u        = (const float*)d_in[22];
    const float* W_c        = (const float*)d_in[23];
    const float* b_c        = (const float*)d_in[24];
    float* outp = (float*)d_out;

    void *vp;
    cudaGetSymbolAddress(&vp, g_s);    float*  ps   = (float*)vp;
    cudaGetSymbolAddress(&vp, g_sh);   __half* psh  = (__half*)vp;
    cudaGetSymbolAddress(&vp, g_qkvh); __half* pqh  = (__half*)vp;
    cudaGetSymbolAddress(&vp, g_sch);  __half* psch = (__half*)vp;
    cudaGetSymbolAddress(&vp, g_adjh); __half* padh = (__half*)vp;
    cudaGetSymbolAddress(&vp, g_oh);   __half* poh  = (__half*)vp;
    cudaGetSymbolAddress(&vp, g_f1);   float*  pf1  = (float*)vp;
    cudaGetSymbolAddress(&vp, g_s2);   float*  ps2  = (float*)vp;
    cudaGetSymbolAddress(&vp, g_s2h);  __half* ps2h = (__half*)vp;
    cudaGetSymbolAddress(&vp, g_poh);  __half* ppoh = (__half*)vp;
    cudaGetSymbolAddress(&vp, g_zh);   __half* pzh  = (__half*)vp;
    cudaGetSymbolAddress(&vp, g_guc);  float*  pguc = (float*)vp;
    cudaGetSymbolAddress(&vp, g_wuch); __half* pwuh = (__half*)vp;
    cudaGetSymbolAddress(&vp, g_buc);  float*  pbuc = (float*)vp;
    cudaGetSymbolAddress(&vp, g_wqh);  __half* pwq  = (__half*)vp;
    cudaGetSymbolAddress(&vp, g_woh);  __half* pwo  = (__half*)vp;
    cudaGetSymbolAddress(&vp, g_w1h);  __half* pw1  = (__half*)vp;
    cudaGetSymbolAddress(&vp, g_w2h);  __half* pw2  = (__half*)vp;

    static const int SMH = NST * STG_H * 2;   // 221184 bytes
    cudaFuncSetAttribute(hgemm, cudaFuncAttributeMaxDynamicSharedMemorySize, SMH);

    // 0. merged prep
    prep_all<<<(PR6 + 255) / 256, 256>>>(in_proj_w, out_proj_w, ffn_w1, ffn_w2,
                                         W_u, W_c, b_u, b_c, adj);

    // 1. transformer input + Z0 x-part (merged)
    trans_hx<<<dim3(7, 10, B_), dim3(32, 8)>>>(h, x, embed, mlt);

    // 2. QKV -> fp16
    hgemm<<<dim3(3, 414, 1), 512, SMH>>>(psh, pwq, in_proj_b, pqh,
        NB_, QKVLD, 256, 256, 256, QKVLD, 0, 0, 0, 1.f, 1, 0, 1, 0, 0);

    // 3. scores: per-batch Q @ K^T / 16 -> fp16
    hgemm<<<dim3(1, 2, B_), 512, SMH>>>(pqh, pqh + 256, nullptr, psch,
        N_, N_, 256, QKVLD, QKVLD, SCLD,
        (long long)N_ * QKVLD, (long long)N_ * QKVLD, (long long)N_ * SCLD,
        1.f / 16.f, 1, 0, 1, 0, 0);

    // 4. softmax in-place on fp16
    softmax_rows<<<NB_ / 8, dim3(32, 8)>>>(psch);

    // 5. attn @ V (NN) -> fp16
    hgemm<<<dim3(1, 2, B_), 512, SMH>>>(psch, pqh + 512, nullptr, poh,
        N_, 256, N_, SCLD, QKVLD, 256,
        (long long)N_ * SCLD, (long long)N_ * QKVLD, (long long)N_ * 256,
        1.f, 0, 0, 1, 0, 0);

    // 6. out projection -> fp32
    hgemm<<<dim3(1, 414, 1), 512, SMH>>>(poh, pwo, out_proj_b, pf1,
        NB_, 256, 256, 256, 256, 256, 0, 0, 0, 1.f, 1, 0, 0, 0, 0);

    // 7. LN1
    add_ln<<<NB_, 256>>>(ps, pf1, ln1_w, ln1_b, ps2, ps2h);

    // 8. FFN
    hgemm<<<dim3(1, 414, 1), 512, SMH>>>(ps2h, pw1, ffn_b1, ppoh,
        NB_, 256, 256, 256, 256, 256, 0, 0, 0, 1.f, 1, 1, 1, 0, 0);
    hgemm<<<dim3(1, 414, 1), 512, SMH>>>(ppoh, pw2, ffn_b2, pf1,
        NB_, 256, 256, 256, 256, 256, 0, 0, 0, 1.f, 1, 0, 0, 0, 0);

    // 9+10. LN2 + h update + Z0 h-part
    ln2_make_h<<<NB_, 256>>>(ps2, pf1, ln2_w, ln2_b, embed, mlt, delta_t, step);

    // 11. diffusion: Z_k = adj @ Z_{k-1}, dense NN (207 x 81920 x 207) -> fp16
    for (int k = 1; k <= 3; ++k) {
        hgemm<<<dim3(ZROW / 256, 2, 1), 512, SMH>>>(padh,
            pzh + (size_t)(k - 1) * ZK, nullptr, pzh + (size_t)k * ZK,
            N_, ZROW, N_, SCLD, ZROW, ZROW,
            0, 0, 0, 1.f, 0, 0, 1, 0, 0);
    }

    // 12. fused gates (blocked-K z) -> fp32
    hgemm<<<dim3(2, 414, 1), 512, SMH>>>(pzh, pwuh, pbuc, pguc,
        NB_, 512, KC_, CXG_, KC_, 512, 0, 0, 0, 1.f, 1, 0, 0,
        CXG_, (long long)ZK - CXG_);

    // 13. gated combine + transpose
    final_combine<<<dim3(7, 8, B_), dim3(32, 8)>>>(outp);
}

// round 15
// speedup vs baseline: 1.0982x; 1.0257x over previous
#include <cuda_runtime.h>
#include <cuda_fp16.h>
#include <math.h>
#include <stdint.h>

// Problem constants
#define B_    256
#define N_    207
#define D_    256
#define DIN_  64
#define CXG_  320
#define KC_   1280
#define NB_   52992
#define QKVLD 768
#define SCLD  208
#define ZROW  81920
#define ZK    ((size_t)NB_ * CXG_)

// ---------------- scratch ----------------
__device__ float  g_s   [(size_t)NB_ * D_];
__device__ __half g_sh  [(size_t)NB_ * D_];
__device__ __half g_qkvh[(size_t)NB_ * QKVLD];
__device__ __half g_sch [(size_t)B_ * N_ * SCLD + 256];
__device__ __half g_adjh[(size_t)N_ * SCLD];
__device__ __half g_oh  [(size_t)NB_ * D_];
__device__ float  g_f1  [(size_t)NB_ * D_];
__device__ float  g_s2  [(size_t)NB_ * D_];
__device__ __half g_s2h [(size_t)NB_ * D_];
__device__ __half g_poh [(size_t)NB_ * D_];
__device__ float  g_hn  [(size_t)NB_ * D_];
__device__ __half g_zh  [4 * ZK];
__device__ float  g_guc [(size_t)NB_ * 512];
__device__ __half g_wuch[(size_t)512 * KC_];
__device__ float  g_buc [512];
__device__ __half g_wqh [(size_t)QKVLD * D_];
__device__ __half g_woh [(size_t)D_ * D_];
__device__ __half g_w1h [(size_t)D_ * D_];
__device__ __half g_w2h [(size_t)D_ * D_];

// ---------------- helpers ----------------
__device__ __forceinline__ void cpa16(void* dst, const void* src, int srcbytes) {
    unsigned d = (unsigned)__cvta_generic_to_shared(dst);
    asm volatile("cp.async.cg.shared.global [%0], [%1], 16, %2;\n"
                 :: "r"(d), "l"(src), "r"(srcbytes));
}
__device__ __forceinline__ void cp_commit() {
    asm volatile("cp.async.commit_group;\n" ::: "memory");
}
template <int NGRP>
__device__ __forceinline__ void cp_wait() {
    asm volatile("cp.async.wait_group %0;\n" :: "n"(NGRP) : "memory");
}

__device__ __forceinline__ void mma_f16(float* c, const unsigned* a, const unsigned* b) {
    asm volatile(
        "mma.sync.aligned.m16n8k16.row.col.f32.f16.f16.f32 "
        "{%0,%1,%2,%3}, {%4,%5,%6,%7}, {%8,%9}, {%0,%1,%2,%3};\n"
        : "+f"(c[0]), "+f"(c[1]), "+f"(c[2]), "+f"(c[3])
        : "r"(a[0]), "r"(a[1]), "r"(a[2]), "r"(a[3]), "r"(b[0]), "r"(b[1]));
}

#define LDSM_X4(r0, r1, r2, r3, a) \
    asm volatile("ldmatrix.sync.aligned.m8n8.x4.shared.b16 {%0,%1,%2,%3}, [%4];" \
                 : "=r"(r0), "=r"(r1), "=r"(r2), "=r"(r3) : "r"(a))
#define LDSM_X4_T(r0, r1, r2, r3, a) \
    asm volatile("ldmatrix.sync.aligned.m8n8.x4.trans.shared.b16 {%0,%1,%2,%3}, [%4];" \
                 : "=r"(r0), "=r"(r1), "=r"(r2), "=r"(r3) : "r"(a))

// ---------------- FP16 tensor-core GEMM ----------------
// BM=128, BN=256, BK=64 halfs, 16 warps (512 thr), warp tile 32x64, m16n8k16,
// LDSM fragments (hoisted base offsets), 4-stage cp.async (dist 2), one barrier.
// TRANSB template: 1 -> B is Nc x K row-major; 0 -> B is K x Nc row-major.
#define AS_H   (128 * 72)
#define BS_H   (256 * 72)      // >= 64*264
#define STG_H  (AS_H + BS_H)
#define NST    4

template<int TRANSB>
__device__ __forceinline__ void load_chunk_h(
    __half* As, __half* Bs, const __half* Ab, const __half* Bb,
    int i0, int j0, int M, int Nc, int K, int lda, int ldb,
    int k0, int tid)
{
#pragma unroll
    for (int l = 0; l < 2; ++l) {
        int e = tid + l * 512;
        int row = e >> 3, q = e & 7;
        int gr = i0 + row; if (gr > M - 1) gr = M - 1;
        int gk = k0 + q * 8;
        int rem = K - gk;
        int bytes = rem >= 8 ? 16 : (rem > 0 ? rem * 2 : 0);
        cpa16(As + row * 72 + q * 8, Ab + (size_t)gr * lda + (bytes ? gk : 0), bytes);
    }
    if (TRANSB) {
#pragma unroll
        for (int l = 0; l < 4; ++l) {
            int e = tid + l * 512;
            int row = e >> 3, q = e & 7;
            int gr = j0 + row; if (gr > Nc - 1) gr = Nc - 1;
            int gk = k0 + q * 8;
            int rem = K - gk;
            int bytes = rem >= 8 ? 16 : (rem > 0 ? rem * 2 : 0);
            cpa16(Bs + row * 72 + q * 8, Bb + (size_t)gr * ldb + (bytes ? gk : 0), bytes);
        }
    } else {
#pragma unroll
        for (int l = 0; l < 4; ++l) {
            int e = tid + l * 512;
            int kk = e >> 5;
            int nq = (e & 31) * 8;
            int gk = k0 + kk;
            int bytes = (gk < K) ? 16 : 0;
            cpa16(Bs + kk * 264 + nq, Bb + (size_t)(bytes ? gk : 0) * ldb + j0 + nq, bytes);
        }
    }
}

template<int TRANSB>
__global__ __launch_bounds__(512, 1) void hgemm(
    const __half* __restrict__ A, const __half* __restrict__ Bm,
    const float* __restrict__ bias, void* __restrict__ Cp,
    int M, int Nc, int K, int lda, int ldb, int ldc,
    long long sA, long long sB, long long sC,
    float alpha, int relu, int outHalf,
    int aksub, long long akstr)
{
    extern __shared__ __half smh[];
    const uint32_t sbase = (uint32_t)__cvta_generic_to_shared(smh);

    const __half* Ab = A  + (size_t)blockIdx.z * sA;
    const __half* Bb = Bm + (size_t)blockIdx.z * sB;

    const int tid  = threadIdx.x;
    const int lane = tid & 31;
    const int wid  = tid >> 5;
    const int wr   = (wid & 3) * 32;
    const int wc   = (wid >> 2) * 64;
    const int g    = lane >> 2;
    const int t    = lane & 3;

    const int i0 = blockIdx.y * 128;
    const int j0 = blockIdx.x * 256;

    float acc[2][8][4];
#pragma unroll
    for (int mi = 0; mi < 2; ++mi)
#pragma unroll
        for (int ni = 0; ni < 8; ++ni)
#pragma unroll
            for (int q = 0; q < 4; ++q) acc[mi][ni][q] = 0.f;

    const int nk = (K + 63) / 64;

#pragma unroll
    for (int s = 0; s < 2; ++s) {
        if (s < nk) {
            const __half* AbC = Ab + (aksub ? (long long)((s * 64) / aksub) * akstr : 0);
            load_chunk_h<TRANSB>(smh + s * STG_H, smh + s * STG_H + AS_H, AbC, Bb,
                                 i0, j0, M, Nc, K, lda, ldb, s * 64, tid);
        }
        cp_commit();
    }

    // hoisted per-thread LDSM base offsets (bytes within a stage)
    const int a_row = (lane & 15);
    const int a_ko  = 8 * (lane >> 4);
    uint32_t offA[2];
#pragma unroll
    for (int mi = 0; mi < 2; ++mi)
        offA[mi] = (uint32_t)((wr + mi * 16 + a_row) * 72 + a_ko) * 2;

    uint32_t offB[4];
    if (TRANSB) {
        const int bt_row = (lane & 7) + 8 * ((lane >> 4) & 1);
        const int bt_ko  = 8 * ((lane >> 3) & 1);
#pragma unroll
        for (int np = 0; np < 4; ++np)
            offB[np] = (uint32_t)((wc + np * 16 + bt_row) * 72 + bt_ko) * 2;
    } else {
        const int bn_row = (lane & 7) + 8 * ((lane >> 3) & 1);
        const int bn_co  = 8 * (lane >> 4);
#pragma unroll
        for (int np = 0; np < 4; ++np)
            offB[np] = (uint32_t)(bn_row * 264 + wc + np * 16 + bn_co) * 2;
    }

    for (int c = 0; c < nk; ++c) {
        int pf = c + 2;
        if (pf < nk) {
            int st = pf % NST;
            const __half* AbC = Ab + (aksub ? (long long)((pf * 64) / aksub) * akstr : 0);
            load_chunk_h<TRANSB>(smh + st * STG_H, smh + st * STG_H + AS_H, AbC, Bb,
                                 i0, j0, M, Nc, K, lda, ldb, pf * 64, tid);
        }
        cp_commit();
        cp_wait<2>();
        __syncthreads();

        const uint32_t aoff = sbase + (uint32_t)((c % NST) * STG_H) * 2;
        const uint32_t boff = aoff + AS_H * 2;

#pragma unroll
        for (int k16 = 0; k16 < 4; ++k16) {
            unsigned af[2][4];
#pragma unroll
            for (int mi = 0; mi < 2; ++mi) {
                uint32_t ad = aoff + offA[mi] + (uint32_t)(k16 * 32);   // kb*2
                LDSM_X4(af[mi][0], af[mi][1], af[mi][2], af[mi][3], ad);
            }
            unsigned bf[8][2];
            if (TRANSB) {
#pragma unroll
                for (int np = 0; np < 4; ++np) {
                    uint32_t bd = boff + offB[np] + (uint32_t)(k16 * 32);
                    LDSM_X4(bf[2 * np][0], bf[2 * np][1],
                            bf[2 * np + 1][0], bf[2 * np + 1][1], bd);
                }
            } else {
#pragma unroll
                for (int np = 0; np < 4; ++np) {
                    uint32_t bd = boff + offB[np] + (uint32_t)(k16 * 16 * 264 * 2);
                    LDSM_X4_T(bf[2 * np][0], bf[2 * np][1],
                              bf[2 * np + 1][0], bf[2 * np + 1][1], bd);
                }
            }
#pragma unroll
            for (int mi = 0; mi < 2; ++mi)
#pragma unroll
                for (int ni = 0; ni < 8; ++ni)
                    mma_f16(acc[mi][ni], af[mi], bf[ni]);
        }
    }
    cp_wait<0>();

    // epilogue
    float* Cf = (float*)Cp + (size_t)blockIdx.z * sC;
    __half* Ch = (__half*)Cp + (size_t)blockIdx.z * sC;
#pragma unroll
    for (int mi = 0; mi < 2; ++mi) {
        int r0 = i0 + wr + mi * 16 + g;
#pragma unroll
        for (int ni = 0; ni < 8; ++ni) {
            int c0 = j0 + wc + ni * 8 + 2 * t;
            float b0v = 0.f, b1v = 0.f;
            if (bias && c0 < Nc) { b0v = bias[c0]; b1v = (c0 + 1 < Nc) ? bias[c0 + 1] : 0.f; }
            float v00 = alpha * acc[mi][ni][0] + b0v;
            float v01 = alpha * acc[mi][ni][1] + b1v;
            float v10 = alpha * acc[mi][ni][2] + b0v;
            float v11 = alpha * acc[mi][ni][3] + b1v;
            if (relu) {
                v00 = fmaxf(v00, 0.f); v01 = fmaxf(v01, 0.f);
                v10 = fmaxf(v10, 0.f); v11 = fmaxf(v11, 0.f);
            }
            if (outHalf) {
                if (r0 < M && c0 < Nc)
                    *(__half2*)&Ch[(size_t)r0 * ldc + c0] = __floats2half2_rn(v00, v01);
                if (r0 + 8 < M && c0 < Nc)
                    *(__half2*)&Ch[(size_t)(r0 + 8) * ldc + c0] = __floats2half2_rn(v10, v11);
            } else {
                if (r0 < M) {
                    if (c0 < Nc)     Cf[(size_t)r0 * ldc + c0]     = v00;
                    if (c0 + 1 < Nc) Cf[(size_t)r0 * ldc + c0 + 1] = v01;
                }
                if (r0 + 8 < M) {
                    if (c0 < Nc)     Cf[(size_t)(r0 + 8) * ldc + c0]     = v10;
                    if (c0 + 1 < Nc) Cf[(size_t)(r0 + 8) * ldc + c0 + 1] = v11;
                }
            }
        }
    }
}

// ---------------- elementwise kernels ----------------

#define PR0 (QKVLD * D_)
#define PR1 (PR0 + D_ * D_)
#define PR2 (PR1 + D_ * D_)
#define PR3 (PR2 + D_ * D_)
#define PR4 (PR3 + 512 * KC_)
#define PR5 (PR4 + 512)
#define PR6 (PR5 + N_ * SCLD)
__global__ void prep_all(const float* __restrict__ wq, const float* __restrict__ wo,
                         const float* __restrict__ w1, const float* __restrict__ w2,
                         const float* __restrict__ Wu, const float* __restrict__ Wc,
                         const float* __restrict__ bu, const float* __restrict__ bc,
                         const float* __restrict__ adj) {
    int i = blockIdx.x * 256 + threadIdx.x;
    if (i < PR0) {
        g_wqh[i] = __float2half(wq[i]);
    } else if (i < PR1) {
        int j = i - PR0; g_woh[j] = __float2half(wo[j]);
    } else if (i < PR2) {
        int j = i - PR1; g_w1h[j] = __float2half(w1[j]);
    } else if (i < PR3) {
        int j = i - PR2; g_w2h[j] = __float2half(w2[j]);
    } else if (i < PR4) {
        int j = i - PR3;
        int row = j / KC_, k = j % KC_;
        float v = (row < 256) ? Wu[(size_t)row * KC_ + k] : Wc[(size_t)(row - 256) * KC_ + k];
        g_wuch[j] = __float2half(v);
    } else if (i < PR5) {
        int j = i - PR4;
        g_buc[j] = (j < 256) ? bu[j] : bc[j - 256];
    } else if (i < PR6) {
        int j = i - PR5;
        int r = j / SCLD, c = j % SCLD;
        g_adjh[j] = __float2half((c < N_) ? adj[(size_t)r * N_ + c] : 0.f);
    }
}

__global__ void trans_hx(const float* __restrict__ h, const float* __restrict__ x,
                         const float* __restrict__ embed, const float* __restrict__ mlt) {
    int b = blockIdx.z;
    int n0 = blockIdx.x * 32;
    __shared__ float tile[32][33];
    int tx = threadIdx.x, ty = threadIdx.y;
    if (blockIdx.y < 8) {
        int c0 = blockIdx.y * 32;
#pragma unroll
        for (int l = 0; l < 4; ++l) {
            int c = c0 + ty + l * 8;
            int n = n0 + tx;
            tile[ty + l * 8][tx] = (n < N_) ? h[((size_t)b * D_ + c) * N_ + n] : 0.f;
        }
        __syncthreads();
#pragma unroll
        for (int l = 0; l < 4; ++l) {
            int n = n0 + ty + l * 8;
            if (n < N_) {
                int c = c0 + tx;
                float m = mlt[(size_t)b * N_ + n];
                float v = tile[tx][ty + l * 8] + embed[(size_t)n * D_ + c] * m;
                size_t idx = ((size_t)b * N_ + n) * D_ + c;
                g_s[idx] = v;
                g_sh[idx] = __float2half(v);
            }
        }
    } else {
        int c0 = (blockIdx.y - 8) * 32;
#pragma unroll
        for (int l = 0; l < 4; ++l) {
            int c = c0 + ty + l * 8;
            int n = n0 + tx;
            tile[ty + l * 8][tx] = (n < N_) ? x[((size_t)b * DIN_ + c) * N_ + n] : 0.f;
        }
        __syncthreads();
#pragma unroll
        for (int l = 0; l < 4; ++l) {
            int n = n0 + ty + l * 8;
            if (n < N_)
                g_zh[((size_t)n * B_ + b) * CXG_ + c0 + tx] = __float2half(tile[tx][ty + l * 8]);
        }
    }
}

__global__ void softmax_rows(__half* __restrict__ sch) {
    int row = blockIdx.x * 8 + threadIdx.y;
    __half* p = sch + (size_t)row * SCLD;
    int lane = threadIdx.x;
    float ev[7];
    float mx = -1e30f;
    int cnt = 0;
    for (int j = lane; j < N_; j += 32) {
        float v = __half2float(p[j]);
        ev[cnt++] = v;
        mx = fmaxf(mx, v);
    }
#pragma unroll
    for (int o = 16; o > 0; o >>= 1) mx = fmaxf(mx, __shfl_xor_sync(0xffffffffu, mx, o));
    float sum = 0.f;
    for (int i = 0; i < cnt; ++i) { ev[i] = expf(ev[i] - mx); sum += ev[i]; }
#pragma unroll
    for (int o = 16; o > 0; o >>= 1) sum += __shfl_xor_sync(0xffffffffu, sum, o);
    float inv = 1.f / sum;
    cnt = 0;
    for (int j = lane; j < N_; j += 32) p[j] = __float2half(ev[cnt++] * inv);
}

__device__ __forceinline__ float2 ln_stats(float v, int c, float* red2) {
    float s = v, q = v * v;
#pragma unroll
    for (int o = 16; o > 0; o >>= 1) {
        s += __shfl_xor_sync(0xffffffffu, s, o);
        q += __shfl_xor_sync(0xffffffffu, q, o);
    }
    if ((c & 31) == 0) { red2[(c >> 5) * 2] = s; red2[(c >> 5) * 2 + 1] = q; }
    __syncthreads();
    float ts = 0.f, tq = 0.f;
#pragma unroll
    for (int w = 0; w < 8; ++w) { ts += red2[w * 2]; tq += red2[w * 2 + 1]; }
    float mu = ts * (1.f / 256.f);
    float var = tq * (1.f / 256.f) - mu * mu;
    return make_float2(mu, rsqrtf(var + 1e-5f));
}

__global__ void add_ln(const float* __restrict__ a, const float* __restrict__ bsrc,
                       const float* __restrict__ w, const float* __restrict__ bb,
                       float* __restrict__ outf, __half* __restrict__ outh) {
    int r = blockIdx.x, c = threadIdx.x;
    size_t idx = (size_t)r * D_ + c;
    float v = a[idx] + bsrc[idx];
    __shared__ float red2[16];
    float2 st = ln_stats(v, c, red2);
    float o = (v - st.x) * st.y * w[c] + bb[c];
    outf[idx] = o;
    outh[idx] = __float2half(o);
}

__global__ void ln2_make_h(const float* __restrict__ a, const float* __restrict__ bsrc,
                           const float* __restrict__ w, const float* __restrict__ bb,
                           const float* __restrict__ embed, const float* __restrict__ mlt,
                           const float* __restrict__ dt, const int* __restrict__ step) {
    int r = blockIdx.x, c = threadIdx.x;
    int b = r / N_, n = r % N_;
    size_t idx = (size_t)r * D_ + c;
    float v = a[idx] + bsrc[idx];
    __shared__ float red2[16];
    float2 st = ln_stats(v, c, red2);
    float s3v = (v - st.x) * st.y * w[c] + bb[c];

    float hv = g_s[idx] - embed[(size_t)n * D_ + c] * mlt[(size_t)b * N_ + n];
    float hn;
    if (*step != 0) {
        float d = dt[b];
        hn = sqrtf(1.f - d) * hv - sqrtf(d) * tanhf(s3v);
    } else {
        hn = hv;
    }
    g_hn[idx] = hn;
    g_zh[((size_t)n * B_ + b) * CXG_ + DIN_ + c] = __float2half(hn);
}

__global__ void final_combine(float* __restrict__ outp) {
    int b = blockIdx.z;
    int o0 = blockIdx.y * 32, n0 = blockIdx.x * 32;
    __shared__ float tbuf[32][33];
    int tx = threadIdx.x, ty = threadIdx.y;
#pragma unroll
    for (int s4 = 0; s4 < 4; ++s4) {
        int nl = ty + s4 * 8;
        int n = n0 + nl;
        float val = 0.f;
        if (n < N_) {
            size_t rp = (size_t)n * B_ + b;
            float gu = g_guc[rp * 512 + o0 + tx];
            float gc = g_guc[rp * 512 + 256 + o0 + tx];
            float uu = 1.f / (1.f + expf(-gu));
            float cc = tanhf(gc);
            val = uu * g_hn[((size_t)b * N_ + n) * D_ + o0 + tx] + (1.f - uu) * cc;
        }
        tbuf[nl][tx] = val;
    }
    __syncthreads();
#pragma unroll
    for (int s4 = 0; s4 < 4; ++s4) {
        int ol = ty + s4 * 8;
        int n = n0 + tx;
        if (n < N_)
            outp[((size_t)(b * D_ + o0 + ol)) * N_ + n] = tbuf[tx][ol];
    }
}

// ---------------- launcher ----------------
extern "C" void kernel_launch(void* const* d_in, const int* in_sizes, int n_in,
                              void* d_out, int out_size) {
    const float* x          = (const float*)d_in[0];
    const float* delta_t    = (const float*)d_in[1];
    const float* h          = (const float*)d_in[2];
    const float* adj        = (const float*)d_in[3];
    const float* mlt        = (const float*)d_in[5];
    const int*   step       = (const int*)d_in[7];
    const float* embed      = (const float*)d_in[8];
    const float* in_proj_w  = (const float*)d_in[9];
    const float* in_proj_b  = (const float*)d_in[10];
    const float* out_proj_w = (const float*)d_in[11];
    const float* out_proj_b = (const float*)d_in[12];
    const float* ln1_w      = (const float*)d_in[13];
    const float* ln1_b      = (const float*)d_in[14];
    const float* ln2_w      = (const float*)d_in[15];
    const float* ln2_b      = (const float*)d_in[16];
    const float* ffn_w1     = (const float*)d_in[17];
    const float* ffn_b1     = (const float*)d_in[18];
    const float* ffn_w2     = (const float*)d_in[19];
    const float* ffn_b2     = (const float*)d_in[20];
    const float* W_u        = (const float*)d_in[21];
    const float* b_u        = (const float*)d_in[22];
    const float* W_c        = (const float*)d_in[23];
    const float* b_c        = (const float*)d_in[24];
    float* outp = (float*)d_out;

    void *vp;
    cudaGetSymbolAddress(&vp, g_s);    float*  ps   = (float*)vp;
    cudaGetSymbolAddress(&vp, g_sh);   __half* psh  = (__half*)vp;
    cudaGetSymbolAddress(&vp, g_qkvh); __half* pqh  = (__half*)vp;
    cudaGetSymbolAddress(&vp, g_sch);  __half* psch = (__half*)vp;
    cudaGetSymbolAddress(&vp, g_adjh); __half* padh = (__half*)vp;
    cudaGetSymbolAddress(&vp, g_oh);   __half* poh  = (__half*)vp;
    cudaGetSymbolAddress(&vp, g_f1);   float*  pf1  = (float*)vp;
    cudaGetSymbolAddress(&vp, g_s2);   float*  ps2  = (float*)vp;
    cudaGetSymbolAddress(&vp, g_s2h);  __half* ps2h = (__half*)vp;
    cudaGetSymbolAddress(&vp, g_poh);  __half* ppoh = (__half*)vp;
    cudaGetSymbolAddress(&vp, g_zh);   __half* pzh  = (__half*)vp;
    cudaGetSymbolAddress(&vp, g_guc);  float*  pguc = (float*)vp;
    cudaGetSymbolAddress(&vp, g_wuch); __half* pwuh = (__half*)vp;
    cudaGetSymbolAddress(&vp, g_buc);  float*  pbuc = (float*)vp;
    cudaGetSymbolAddress(&vp, g_wqh);  __half* pwq  = (__half*)vp;
    cudaGetSymbolAddress(&vp, g_woh);  __half* pwo  = (__half*)vp;
    cudaGetSymbolAddress(&vp, g_w1h);  __half* pw1  = (__half*)vp;
    cudaGetSymbolAddress(&vp, g_w2h);  __half* pw2  = (__half*)vp;

    static const int SMH = NST * STG_H * 2;   // 221184 bytes
    cudaFuncSetAttribute(hgemm<0>, cudaFuncAttributeMaxDynamicSharedMemorySize, SMH);
    cudaFuncSetAttribute(hgemm<1>, cudaFuncAttributeMaxDynamicSharedMemorySize, SMH);

    // 0. merged prep
    prep_all<<<(PR6 + 255) / 256, 256>>>(in_proj_w, out_proj_w, ffn_w1, ffn_w2,
                                         W_u, W_c, b_u, b_c, adj);

    // 1. transformer input + Z0 x-part (merged)
    trans_hx<<<dim3(7, 10, B_), dim3(32, 8)>>>(h, x, embed, mlt);

    // 2. QKV -> fp16
    hgemm<1><<<dim3(3, 414, 1), 512, SMH>>>(psh, pwq, in_proj_b, pqh,
        NB_, QKVLD, 256, 256, 256, QKVLD, 0, 0, 0, 1.f, 0, 1, 0, 0);

    // 3. scores: per-batch Q @ K^T / 16 -> fp16
    hgemm<1><<<dim3(1, 2, B_), 512, SMH>>>(pqh, pqh + 256, nullptr, psch,
        N_, N_, 256, QKVLD, QKVLD, SCLD,
        (long long)N_ * QKVLD, (long long)N_ * QKVLD, (long long)N_ * SCLD,
        1.f / 16.f, 0, 1, 0, 0);

    // 4. softmax in-place on fp16
    softmax_rows<<<NB_ / 8, dim3(32, 8)>>>(psch);

    // 5. attn @ V (NN) -> fp16
    hgemm<0><<<dim3(1, 2, B_), 512, SMH>>>(psch, pqh + 512, nullptr, poh,
        N_, 256, N_, SCLD, QKVLD, 256,
        (long long)N_ * SCLD, (long long)N_ * QKVLD, (long long)N_ * 256,
        1.f, 0, 1, 0, 0);

    // 6. out projection -> fp32
    hgemm<1><<<dim3(1, 414, 1), 512, SMH>>>(poh, pwo, out_proj_b, pf1,
        NB_, 256, 256, 256, 256, 256, 0, 0, 0, 1.f, 0, 0, 0, 0);

    // 7. LN1
    add_ln<<<NB_, 256>>>(ps, pf1, ln1_w, ln1_b, ps2, ps2h);

    // 8. FFN
    hgemm<1><<<dim3(1, 414, 1), 512, SMH>>>(ps2h, pw1, ffn_b1, ppoh,
        NB_, 256, 256, 256, 256, 256, 0, 0, 0, 1.f, 1, 1, 0, 0);
    hgemm<1><<<dim3(1, 414, 1), 512, SMH>>>(ppoh, pw2, ffn_b2, pf1,
        NB_, 256, 256, 256, 256, 256, 0, 0, 0, 1.f, 0, 0, 0, 0);

    // 9+10. LN2 + h update + Z0 h-part
    ln2_make_h<<<NB_, 256>>>(ps2, pf1, ln2_w, ln2_b, embed, mlt, delta_t, step);

    // 11. diffusion: Z_k = adj @ Z_{k-1}, dense NN (207 x 81920 x 207) -> fp16
    for (int k = 1; k <= 3; ++k) {
        hgemm<0><<<dim3(ZROW / 256, 2, 1), 512, SMH>>>(padh,
            pzh + (size_t)(k - 1) * ZK, nullptr, pzh + (size_t)k * ZK,
            N_, ZROW, N_, SCLD, ZROW, ZROW,
            0, 0, 0, 1.f, 0, 1, 0, 0);
    }

    // 12. fused gates (blocked-K z) -> fp32
    hgemm<1><<<dim3(2, 414, 1), 512, SMH>>>(pzh, pwuh, pbuc, pguc,
        NB_, 512, KC_, CXG_, KC_, 512, 0, 0, 0, 1.f, 0, 0,
        CXG_, (long long)ZK - CXG_);

    // 13. gated combine + transpose
    final_combine<<<dim3(7, 8, B_), dim3(32, 8)>>>(outp);
}

// round 16
// speedup vs baseline: 1.1172x; 1.0172x over previous
#include <cuda_runtime.h>
#include <cuda_fp16.h>
#include <math.h>
#include <stdint.h>

// Problem constants
#define B_    256
#define N_    207
#define D_    256
#define DIN_  64
#define CXG_  320
#define KC_   1280
#define NB_   52992
#define QKVLD 768
#define SCLD  208
#define ZROW  81920
#define ZK    ((size_t)NB_ * CXG_)

// ---------------- scratch ----------------
__device__ float  g_s   [(size_t)NB_ * D_];
__device__ __half g_sh  [(size_t)NB_ * D_];
__device__ __half g_qkvh[(size_t)NB_ * QKVLD];
__device__ __half g_sch [(size_t)B_ * N_ * SCLD + 256];
__device__ __half g_adjh[3 * (size_t)N_ * SCLD];   // adj, adj^2, adj^3 (fp16, padded)
__device__ __half g_oh  [(size_t)NB_ * D_];
__device__ float  g_f1  [(size_t)NB_ * D_];
__device__ float  g_s2  [(size_t)NB_ * D_];
__device__ __half g_s2h [(size_t)NB_ * D_];
__device__ __half g_poh [(size_t)NB_ * D_];
__device__ float  g_hn  [(size_t)NB_ * D_];
__device__ __half g_zh  [4 * ZK];
__device__ float  g_guc [(size_t)NB_ * 512];
__device__ __half g_wuch[(size_t)512 * KC_];
__device__ float  g_buc [512];
__device__ __half g_wqh [(size_t)QKVLD * D_];
__device__ __half g_woh [(size_t)D_ * D_];
__device__ __half g_w1h [(size_t)D_ * D_];
__device__ __half g_w2h [(size_t)D_ * D_];

// ---------------- helpers ----------------
__device__ __forceinline__ void cpa16(void* dst, const void* src, int srcbytes) {
    unsigned d = (unsigned)__cvta_generic_to_shared(dst);
    asm volatile("cp.async.cg.shared.global [%0], [%1], 16, %2;\n"
                 :: "r"(d), "l"(src), "r"(srcbytes));
}
__device__ __forceinline__ void cp_commit() {
    asm volatile("cp.async.commit_group;\n" ::: "memory");
}
template <int NGRP>
__device__ __forceinline__ void cp_wait() {
    asm volatile("cp.async.wait_group %0;\n" :: "n"(NGRP) : "memory");
}

__device__ __forceinline__ void mma_f16(float* c, const unsigned* a, const unsigned* b) {
    asm volatile(
        "mma.sync.aligned.m16n8k16.row.col.f32.f16.f16.f32 "
        "{%0,%1,%2,%3}, {%4,%5,%6,%7}, {%8,%9}, {%0,%1,%2,%3};\n"
        : "+f"(c[0]), "+f"(c[1]), "+f"(c[2]), "+f"(c[3])
        : "r"(a[0]), "r"(a[1]), "r"(a[2]), "r"(a[3]), "r"(b[0]), "r"(b[1]));
}

#define LDSM_X4(r0, r1, r2, r3, a) \
    asm volatile("ldmatrix.sync.aligned.m8n8.x4.shared.b16 {%0,%1,%2,%3}, [%4];" \
                 : "=r"(r0), "=r"(r1), "=r"(r2), "=r"(r3) : "r"(a))
#define LDSM_X4_T(r0, r1, r2, r3, a) \
    asm volatile("ldmatrix.sync.aligned.m8n8.x4.trans.shared.b16 {%0,%1,%2,%3}, [%4];" \
                 : "=r"(r0), "=r"(r1), "=r"(r2), "=r"(r3) : "r"(a))

// ---------------- FP16 tensor-core GEMM ----------------
#define AS_H   (128 * 72)
#define BS_H   (256 * 72)
#define STG_H  (AS_H + BS_H)
#define NST    4

template<int TRANSB>
__device__ __forceinline__ void load_chunk_h(
    __half* As, __half* Bs, const __half* Ab, const __half* Bb,
    int i0, int j0, int M, int Nc, int K, int lda, int ldb,
    int k0, int tid)
{
#pragma unroll
    for (int l = 0; l < 2; ++l) {
        int e = tid + l * 512;
        int row = e >> 3, q = e & 7;
        int gr = i0 + row; if (gr > M - 1) gr = M - 1;
        int gk = k0 + q * 8;
        int rem = K - gk;
        int bytes = rem >= 8 ? 16 : (rem > 0 ? rem * 2 : 0);
        cpa16(As + row * 72 + q * 8, Ab + (size_t)gr * lda + (bytes ? gk : 0), bytes);
    }
    if (TRANSB) {
#pragma unroll
        for (int l = 0; l < 4; ++l) {
            int e = tid + l * 512;
            int row = e >> 3, q = e & 7;
            int gr = j0 + row; if (gr > Nc - 1) gr = Nc - 1;
            int gk = k0 + q * 8;
            int rem = K - gk;
            int bytes = rem >= 8 ? 16 : (rem > 0 ? rem * 2 : 0);
            cpa16(Bs + row * 72 + q * 8, Bb + (size_t)gr * ldb + (bytes ? gk : 0), bytes);
        }
    } else {
#pragma unroll
        for (int l = 0; l < 4; ++l) {
            int e = tid + l * 512;
            int kk = e >> 5;
            int nq = (e & 31) * 8;
            int gk = k0 + kk;
            int bytes = (gk < K) ? 16 : 0;
            cpa16(Bs + kk * 264 + nq, Bb + (size_t)(bytes ? gk : 0) * ldb + j0 + nq, bytes);
        }
    }
}

template<int TRANSB>
__global__ __launch_bounds__(512, 1) void hgemm(
    const __half* __restrict__ A, const __half* __restrict__ Bm,
    const float* __restrict__ bias, void* __restrict__ Cp,
    int M, int Nc, int K, int lda, int ldb, int ldc,
    long long sA, long long sB, long long sC,
    float alpha, int relu, int outHalf,
    int aksub, long long akstr)
{
    extern __shared__ __half smh[];
    const uint32_t sbase = (uint32_t)__cvta_generic_to_shared(smh);

    const __half* Ab = A  + (size_t)blockIdx.z * sA;
    const __half* Bb = Bm + (size_t)blockIdx.z * sB;

    const int tid  = threadIdx.x;
    const int lane = tid & 31;
    const int wid  = tid >> 5;
    const int wr   = (wid & 3) * 32;
    const int wc   = (wid >> 2) * 64;
    const int g    = lane >> 2;
    const int t    = lane & 3;

    const int i0 = blockIdx.y * 128;
    const int j0 = blockIdx.x * 256;

    float acc[2][8][4];
#pragma unroll
    for (int mi = 0; mi < 2; ++mi)
#pragma unroll
        for (int ni = 0; ni < 8; ++ni)
#pragma unroll
            for (int q = 0; q < 4; ++q) acc[mi][ni][q] = 0.f;

    const int nk = (K + 63) / 64;

#pragma unroll
    for (int s = 0; s < 2; ++s) {
        if (s < nk) {
            const __half* AbC = Ab + (aksub ? (long long)((s * 64) / aksub) * akstr : 0);
            load_chunk_h<TRANSB>(smh + s * STG_H, smh + s * STG_H + AS_H, AbC, Bb,
                                 i0, j0, M, Nc, K, lda, ldb, s * 64, tid);
        }
        cp_commit();
    }

    const int a_row = (lane & 15);
    const int a_ko  = 8 * (lane >> 4);
    uint32_t offA[2];
#pragma unroll
    for (int mi = 0; mi < 2; ++mi)
        offA[mi] = (uint32_t)((wr + mi * 16 + a_row) * 72 + a_ko) * 2;

    uint32_t offB[4];
    if (TRANSB) {
        const int bt_row = (lane & 7) + 8 * ((lane >> 4) & 1);
        const int bt_ko  = 8 * ((lane >> 3) & 1);
#pragma unroll
        for (int np = 0; np < 4; ++np)
            offB[np] = (uint32_t)((wc + np * 16 + bt_row) * 72 + bt_ko) * 2;
    } else {
        const int bn_row = (lane & 7) + 8 * ((lane >> 3) & 1);
        const int bn_co  = 8 * (lane >> 4);
#pragma unroll
        for (int np = 0; np < 4; ++np)
            offB[np] = (uint32_t)(bn_row * 264 + wc + np * 16 + bn_co) * 2;
    }

    for (int c = 0; c < nk; ++c) {
        int pf = c + 2;
        if (pf < nk) {
            int st = pf % NST;
            const __half* AbC = Ab + (aksub ? (long long)((pf * 64) / aksub) * akstr : 0);
            load_chunk_h<TRANSB>(smh + st * STG_H, smh + st * STG_H + AS_H, AbC, Bb,
                                 i0, j0, M, Nc, K, lda, ldb, pf * 64, tid);
        }
        cp_commit();
        cp_wait<2>();
        __syncthreads();

        const uint32_t aoff = sbase + (uint32_t)((c % NST) * STG_H) * 2;
        const uint32_t boff = aoff + AS_H * 2;

#pragma unroll
        for (int k16 = 0; k16 < 4; ++k16) {
            unsigned af[2][4];
#pragma unroll
            for (int mi = 0; mi < 2; ++mi) {
                uint32_t ad = aoff + offA[mi] + (uint32_t)(k16 * 32);
                LDSM_X4(af[mi][0], af[mi][1], af[mi][2], af[mi][3], ad);
            }
            unsigned bf[8][2];
            if (TRANSB) {
#pragma unroll
                for (int np = 0; np < 4; ++np) {
                    uint32_t bd = boff + offB[np] + (uint32_t)(k16 * 32);
                    LDSM_X4(bf[2 * np][0], bf[2 * np][1],
                            bf[2 * np + 1][0], bf[2 * np + 1][1], bd);
                }
            } else {
#pragma unroll
                for (int np = 0; np < 4; ++np) {
                    uint32_t bd = boff + offB[np] + (uint32_t)(k16 * 16 * 264 * 2);
                    LDSM_X4_T(bf[2 * np][0], bf[2 * np][1],
                              bf[2 * np + 1][0], bf[2 * np + 1][1], bd);
                }
            }
#pragma unroll
            for (int mi = 0; mi < 2; ++mi)
#pragma unroll
                for (int ni = 0; ni < 8; ++ni)
                    mma_f16(acc[mi][ni], af[mi], bf[ni]);
        }
    }
    cp_wait<0>();

    // epilogue
    float* Cf = (float*)Cp + (size_t)blockIdx.z * sC;
    __half* Ch = (__half*)Cp + (size_t)blockIdx.z * sC;
#pragma unroll
    for (int mi = 0; mi < 2; ++mi) {
        int r0 = i0 + wr + mi * 16 + g;
#pragma unroll
        for (int ni = 0; ni < 8; ++ni) {
            int c0 = j0 + wc + ni * 8 + 2 * t;
            float b0v = 0.f, b1v = 0.f;
            if (bias && c0 < Nc) { b0v = bias[c0]; b1v = (c0 + 1 < Nc) ? bias[c0 + 1] : 0.f; }
            float v00 = alpha * acc[mi][ni][0] + b0v;
            float v01 = alpha * acc[mi][ni][1] + b1v;
            float v10 = alpha * acc[mi][ni][2] + b0v;
            float v11 = alpha * acc[mi][ni][3] + b1v;
            if (relu) {
                v00 = fmaxf(v00, 0.f); v01 = fmaxf(v01, 0.f);
                v10 = fmaxf(v10, 0.f); v11 = fmaxf(v11, 0.f);
            }
            if (outHalf) {
                if (r0 < M && c0 < Nc)
                    *(__half2*)&Ch[(size_t)r0 * ldc + c0] = __floats2half2_rn(v00, v01);
                if (r0 + 8 < M && c0 < Nc)
                    *(__half2*)&Ch[(size_t)(r0 + 8) * ldc + c0] = __floats2half2_rn(v10, v11);
            } else {
                if (r0 < M) {
                    if (c0 < Nc)     Cf[(size_t)r0 * ldc + c0]     = v00;
                    if (c0 + 1 < Nc) Cf[(size_t)r0 * ldc + c0 + 1] = v01;
                }
                if (r0 + 8 < M) {
                    if (c0 < Nc)     Cf[(size_t)(r0 + 8) * ldc + c0]     = v10;
                    if (c0 + 1 < Nc) Cf[(size_t)(r0 + 8) * ldc + c0 + 1] = v11;
                }
            }
        }
    }
}

// ---------------- elementwise kernels ----------------

#define PR0 (QKVLD * D_)
#define PR1 (PR0 + D_ * D_)
#define PR2 (PR1 + D_ * D_)
#define PR3 (PR2 + D_ * D_)
#define PR4 (PR3 + 512 * KC_)
#define PR5 (PR4 + 512)
#define PR6 (PR5 + N_ * SCLD)
__global__ void prep_all(const float* __restrict__ wq, const float* __restrict__ wo,
                         const float* __restrict__ w1, const float* __restrict__ w2,
                         const float* __restrict__ Wu, const float* __restrict__ Wc,
                         const float* __restrict__ bu, const float* __restrict__ bc,
                         const float* __restrict__ adj) {
    int i = blockIdx.x * 256 + threadIdx.x;
    if (i < PR0) {
        g_wqh[i] = __float2half(wq[i]);
    } else if (i < PR1) {
        int j = i - PR0; g_woh[j] = __float2half(wo[j]);
    } else if (i < PR2) {
        int j = i - PR1; g_w1h[j] = __float2half(w1[j]);
    } else if (i < PR3) {
        int j = i - PR2; g_w2h[j] = __float2half(w2[j]);
    } else if (i < PR4) {
        int j = i - PR3;
        int row = j / KC_, k = j % KC_;
        float v = (row < 256) ? Wu[(size_t)row * KC_ + k] : Wc[(size_t)(row - 256) * KC_ + k];
        g_wuch[j] = __float2half(v);
    } else if (i < PR5) {
        int j = i - PR4;
        g_buc[j] = (j < 256) ? bu[j] : bc[j - 256];
    } else if (i < PR6) {
        int j = i - PR5;
        int r = j / SCLD, c = j % SCLD;
        g_adjh[j] = __float2half((c < N_) ? adj[(size_t)r * N_ + c] : 0.f);
    }
}

__global__ void trans_hx(const float* __restrict__ h, const float* __restrict__ x,
                         const float* __restrict__ embed, const float* __restrict__ mlt) {
    int b = blockIdx.z;
    int n0 = blockIdx.x * 32;
    __shared__ float tile[32][33];
    int tx = threadIdx.x, ty = threadIdx.y;
    if (blockIdx.y < 8) {
        int c0 = blockIdx.y * 32;
#pragma unroll
        for (int l = 0; l < 4; ++l) {
            int c = c0 + ty + l * 8;
            int n = n0 + tx;
            tile[ty + l * 8][tx] = (n < N_) ? h[((size_t)b * D_ + c) * N_ + n] : 0.f;
        }
        __syncthreads();
#pragma unroll
        for (int l = 0; l < 4; ++l) {
            int n = n0 + ty + l * 8;
            if (n < N_) {
                int c = c0 + tx;
                float m = mlt[(size_t)b * N_ + n];
                float v = tile[tx][ty + l * 8] + embed[(size_t)n * D_ + c] * m;
                size_t idx = ((size_t)b * N_ + n) * D_ + c;
                g_s[idx] = v;
                g_sh[idx] = __float2half(v);
            }
        }
    } else {
        int c0 = (blockIdx.y - 8) * 32;
#pragma unroll
        for (int l = 0; l < 4; ++l) {
            int c = c0 + ty + l * 8;
            int n = n0 + tx;
            tile[ty + l * 8][tx] = (n < N_) ? x[((size_t)b * DIN_ + c) * N_ + n] : 0.f;
        }
        __syncthreads();
#pragma unroll
        for (int l = 0; l < 4; ++l) {
            int n = n0 + ty + l * 8;
            if (n < N_)
                g_zh[((size_t)n * B_ + b) * CXG_ + c0 + tx] = __float2half(tile[tx][ty + l * 8]);
        }
    }
}

__global__ void softmax_rows(__half* __restrict__ sch) {
    int row = blockIdx.x * 8 + threadIdx.y;
    __half* p = sch + (size_t)row * SCLD;
    int lane = threadIdx.x;
    float ev[7];
    float mx = -1e30f;
    int cnt = 0;
    for (int j = lane; j < N_; j += 32) {
        float v = __half2float(p[j]);
        ev[cnt++] = v;
        mx = fmaxf(mx, v);
    }
#pragma unroll
    for (int o = 16; o > 0; o >>= 1) mx = fmaxf(mx, __shfl_xor_sync(0xffffffffu, mx, o));
    float sum = 0.f;
    for (int i = 0; i < cnt; ++i) { ev[i] = expf(ev[i] - mx); sum += ev[i]; }
#pragma unroll
    for (int o = 16; o > 0; o >>= 1) sum += __shfl_xor_sync(0xffffffffu, sum, o);
    float inv = 1.f / sum;
    cnt = 0;
    for (int j = lane; j < N_; j += 32) p[j] = __float2half(ev[cnt++] * inv);
}

__device__ __forceinline__ float2 ln_stats(float v, int c, float* red2) {
    float s = v, q = v * v;
#pragma unroll
    for (int o = 16; o > 0; o >>= 1) {
        s += __shfl_xor_sync(0xffffffffu, s, o);
        q += __shfl_xor_sync(0xffffffffu, q, o);
    }
    if ((c & 31) == 0) { red2[(c >> 5) * 2] = s; red2[(c >> 5) * 2 + 1] = q; }
    __syncthreads();
    float ts = 0.f, tq = 0.f;
#pragma unroll
    for (int w = 0; w < 8; ++w) { ts += red2[w * 2]; tq += red2[w * 2 + 1]; }
    float mu = ts * (1.f / 256.f);
    float var = tq * (1.f / 256.f) - mu * mu;
    return make_float2(mu, rsqrtf(var + 1e-5f));
}

__global__ void add_ln(const float* __restrict__ a, const float* __restrict__ bsrc,
                       const float* __restrict__ w, const float* __restrict__ bb,
                       float* __restrict__ outf, __half* __restrict__ outh) {
    int r = blockIdx.x, c = threadIdx.x;
    size_t idx = (size_t)r * D_ + c;
    float v = a[idx] + bsrc[idx];
    __shared__ float red2[16];
    float2 st = ln_stats(v, c, red2);
    float o = (v - st.x) * st.y * w[c] + bb[c];
    outf[idx] = o;
    outh[idx] = __float2half(o);
}

__global__ void ln2_make_h(const float* __restrict__ a, const float* __restrict__ bsrc,
                           const float* __restrict__ w, const float* __restrict__ bb,
                           const float* __restrict__ embed, const float* __restrict__ mlt,
                           const float* __restrict__ dt, const int* __restrict__ step) {
    int r = blockIdx.x, c = threadIdx.x;
    int b = r / N_, n = r % N_;
    size_t idx = (size_t)r * D_ + c;
    float v = a[idx] + bsrc[idx];
    __shared__ float red2[16];
    float2 st = ln_stats(v, c, red2);
    float s3v = (v - st.x) * st.y * w[c] + bb[c];

    float hv = g_s[idx] - embed[(size_t)n * D_ + c] * mlt[(size_t)b * N_ + n];
    float hn;
    if (*step != 0) {
        float d = dt[b];
        hn = sqrtf(1.f - d) * hv - sqrtf(d) * tanhf(s3v);
    } else {
        hn = hv;
    }
    g_hn[idx] = hn;
    g_zh[((size_t)n * B_ + b) * CXG_ + DIN_ + c] = __float2half(hn);
}

__global__ void final_combine(float* __restrict__ outp) {
    int b = blockIdx.z;
    int o0 = blockIdx.y * 32, n0 = blockIdx.x * 32;
    __shared__ float tbuf[32][33];
    int tx = threadIdx.x, ty = threadIdx.y;
#pragma unroll
    for (int s4 = 0; s4 < 4; ++s4) {
        int nl = ty + s4 * 8;
        int n = n0 + nl;
        float val = 0.f;
        if (n < N_) {
            size_t rp = (size_t)n * B_ + b;
            float gu = g_guc[rp * 512 + o0 + tx];
            float gc = g_guc[rp * 512 + 256 + o0 + tx];
            float uu = 1.f / (1.f + expf(-gu));
            float cc = tanhf(gc);
            val = uu * g_hn[((size_t)b * N_ + n) * D_ + o0 + tx] + (1.f - uu) * cc;
        }
        tbuf[nl][tx] = val;
    }
    __syncthreads();
#pragma unroll
    for (int s4 = 0; s4 < 4; ++s4) {
        int ol = ty + s4 * 8;
        int n = n0 + tx;
        if (n < N_)
            outp[((size_t)(b * D_ + o0 + ol)) * N_ + n] = tbuf[tx][ol];
    }
}

// ---------------- launcher ----------------
extern "C" void kernel_launch(void* const* d_in, const int* in_sizes, int n_in,
                              void* d_out, int out_size) {
    const float* x          = (const float*)d_in[0];
    const float* delta_t    = (const float*)d_in[1];
    const float* h          = (const float*)d_in[2];
    const float* adj        = (const float*)d_in[3];
    const float* mlt        = (const float*)d_in[5];
    const int*   step       = (const int*)d_in[7];
    const float* embed      = (const float*)d_in[8];
    const float* in_proj_w  = (const float*)d_in[9];
    const float* in_proj_b  = (const float*)d_in[10];
    const float* out_proj_w = (const float*)d_in[11];
    const float* out_proj_b = (const float*)d_in[12];
    const float* ln1_w      = (const float*)d_in[13];
    const float* ln1_b      = (const float*)d_in[14];
    const float* ln2_w      = (const float*)d_in[15];
    const float* ln2_b      = (const float*)d_in[16];
    const float* ffn_w1     = (const float*)d_in[17];
    const float* ffn_b1     = (const float*)d_in[18];
    const float* ffn_w2     = (const float*)d_in[19];
    const float* ffn_b2     = (const float*)d_in[20];
    const float* W_u        = (const float*)d_in[21];
    const float* b_u        = (const float*)d_in[22];
    const float* W_c        = (const float*)d_in[23];
    const float* b_c        = (const float*)d_in[24];
    float* outp = (float*)d_out;

    void *vp;
    cudaGetSymbolAddress(&vp, g_s);    float*  ps   = (float*)vp;
    cudaGetSymbolAddress(&vp, g_sh);   __half* psh  = (__half*)vp;
    cudaGetSymbolAddress(&vp, g_qkvh); __half* pqh  = (__half*)vp;
    cudaGetSymbolAddress(&vp, g_sch);  __half* psch = (__half*)vp;
    cudaGetSymbolAddress(&vp, g_adjh); __half* padh = (__half*)vp;
    cudaGetSymbolAddress(&vp, g_oh);   __half* poh  = (__half*)vp;
    cudaGetSymbolAddress(&vp, g_f1);   float*  pf1  = (float*)vp;
    cudaGetSymbolAddress(&vp, g_s2);   float*  ps2  = (float*)vp;
    cudaGetSymbolAddress(&vp, g_s2h);  __half* ps2h = (__half*)vp;
    cudaGetSymbolAddress(&vp, g_poh);  __half* ppoh = (__half*)vp;
    cudaGetSymbolAddress(&vp, g_zh);   __half* pzh  = (__half*)vp;
    cudaGetSymbolAddress(&vp, g_guc);  float*  pguc = (float*)vp;
    cudaGetSymbolAddress(&vp, g_wuch); __half* pwuh = (__half*)vp;
    cudaGetSymbolAddress(&vp, g_buc);  float*  pbuc = (float*)vp;
    cudaGetSymbolAddress(&vp, g_wqh);  __half* pwq  = (__half*)vp;
    cudaGetSymbolAddress(&vp, g_woh);  __half* pwo  = (__half*)vp;
    cudaGetSymbolAddress(&vp, g_w1h);  __half* pw1  = (__half*)vp;
    cudaGetSymbolAddress(&vp, g_w2h);  __half* pw2  = (__half*)vp;

    __half* padj2 = padh + (size_t)N_ * SCLD;
    __half* padj3 = padh + 2 * (size_t)N_ * SCLD;

    static const int SMH = NST * STG_H * 2;   // 221184 bytes
    cudaFuncSetAttribute(hgemm<0>, cudaFuncAttributeMaxDynamicSharedMemorySize, SMH);
    cudaFuncSetAttribute(hgemm<1>, cudaFuncAttributeMaxDynamicSharedMemorySize, SMH);

    // 0. merged prep (adj -> fp16 slot 0)
    prep_all<<<(PR6 + 255) / 256, 256>>>(in_proj_w, out_proj_w, ffn_w1, ffn_w2,
                                         W_u, W_c, b_u, b_c, adj);

    // 0b. adj powers: adj^2 = adj @ adj, adj^3 = adj^2 @ adj (tiny fp16 GEMMs)
    hgemm<0><<<dim3(1, 2, 1), 512, SMH>>>(padh, padh, nullptr, padj2,
        N_, N_, N_, SCLD, SCLD, SCLD, 0, 0, 0, 1.f, 0, 1, 0, 0);
    hgemm<0><<<dim3(1, 2, 1), 512, SMH>>>(padj2, padh, nullptr, padj3,
        N_, N_, N_, SCLD, SCLD, SCLD, 0, 0, 0, 1.f, 0, 1, 0, 0);

    // 1. transformer input + Z0 x-part (merged)
    trans_hx<<<dim3(7, 10, B_), dim3(32, 8)>>>(h, x, embed, mlt);

    // 2. QKV -> fp16
    hgemm<1><<<dim3(3, 414, 1), 512, SMH>>>(psh, pwq, in_proj_b, pqh,
        NB_, QKVLD, 256, 256, 256, QKVLD, 0, 0, 0, 1.f, 0, 1, 0, 0);

    // 3. scores: per-batch Q @ K^T / 16 -> fp16
    hgemm<1><<<dim3(1, 2, B_), 512, SMH>>>(pqh, pqh + 256, nullptr, psch,
        N_, N_, 256, QKVLD, QKVLD, SCLD,
        (long long)N_ * QKVLD, (long long)N_ * QKVLD, (long long)N_ * SCLD,
        1.f / 16.f, 0, 1, 0, 0);

    // 4. softmax in-place
    softmax_rows<<<NB_ / 8, dim3(32, 8)>>>(psch);

    // 5. attn @ V (NN) -> fp16
    hgemm<0><<<dim3(1, 2, B_), 512, SMH>>>(psch, pqh + 512, nullptr, poh,
        N_, 256, N_, SCLD, QKVLD, 256,
        (long long)N_ * SCLD, (long long)N_ * QKVLD, (long long)N_ * 256,
        1.f, 0, 1, 0, 0);

    // 6. out projection -> fp32
    hgemm<1><<<dim3(1, 414, 1), 512, SMH>>>(poh, pwo, out_proj_b, pf1,
        NB_, 256, 256, 256, 256, 256, 0, 0, 0, 1.f, 0, 0, 0, 0);

    // 7. LN1
    add_ln<<<NB_, 256>>>(ps, pf1, ln1_w, ln1_b, ps2, ps2h);

    // 8. FFN
    hgemm<1><<<dim3(1, 414, 1), 512, SMH>>>(ps2h, pw1, ffn_b1, ppoh,
        NB_, 256, 256, 256, 256, 256, 0, 0, 0, 1.f, 1, 1, 0, 0);
    hgemm<1><<<dim3(1, 414, 1), 512, SMH>>>(ppoh, pw2, ffn_b2, pf1,
        NB_, 256, 256, 256, 256, 256, 0, 0, 0, 1.f, 0, 0, 0, 0);

    // 9+10. LN2 + h update + Z0 h-part
    ln2_make_h<<<NB_, 256>>>(ps2, pf1, ln2_w, ln2_b, embed, mlt, delta_t, step);

    // 11. diffusion: Z_k = adj^k @ Z0, ONE batched launch over k=1..3
    hgemm<0><<<dim3(ZROW / 256, 2, 3), 512, SMH>>>(padh, pzh, nullptr, pzh + ZK,
        N_, ZROW, N_, SCLD, ZROW, ZROW,
        (long long)N_ * SCLD, 0, (long long)ZK,
        1.f, 0, 1, 0, 0);

    // 12. fused gates (blocked-K z) -> fp32
    hgemm<1><<<dim3(2, 414, 1), 512, SMH>>>(pzh, pwuh, pbuc, pguc,
        NB_, 512, KC_, CXG_, KC_, 512, 0, 0, 0, 1.f, 0, 0,
        CXG_, (long long)ZK - CXG_);

    // 13. gated combine + transpose
    final_combine<<<dim3(7, 8, B_), dim3(32, 8)>>>(outp);
}

// round 17
// speedup vs baseline: 1.1229x; 1.0051x over previous
#include <cuda_runtime.h>
#include <cuda_fp16.h>
#include <math.h>
#include <stdint.h>

// Problem constants
#define B_    256
#define N_    207
#define D_    256
#define DIN_  64
#define CXG_  320
#define KC_   1280
#define NB_   52992
#define QKVLD 768
#define SCLD  208
#define ZROW  81920
#define ZK    ((size_t)NB_ * CXG_)

// ---------------- scratch ----------------
__device__ float  g_s   [(size_t)NB_ * D_];
__device__ __half g_sh  [(size_t)NB_ * D_];
__device__ __half g_qkvh[(size_t)NB_ * QKVLD];
__device__ __half g_sch [(size_t)B_ * N_ * SCLD + 256];
__device__ __half g_adjh[3 * (size_t)N_ * SCLD];   // adj, adj^2, adj^3
__device__ __half g_oh  [(size_t)NB_ * D_];
__device__ float  g_f1  [(size_t)NB_ * D_];
__device__ float  g_s2  [(size_t)NB_ * D_];
__device__ __half g_s2h [(size_t)NB_ * D_];
__device__ __half g_poh [(size_t)NB_ * D_];
__device__ float  g_hn  [(size_t)NB_ * D_];
__device__ __half g_zh  [4 * ZK];
__device__ float  g_guc [(size_t)NB_ * 512];
__device__ __half g_wuch[(size_t)512 * KC_];
__device__ float  g_buc [512];
__device__ __half g_wqh [(size_t)QKVLD * D_];
__device__ __half g_woh [(size_t)D_ * D_];
__device__ __half g_w1h [(size_t)D_ * D_];
__device__ __half g_w2h [(size_t)D_ * D_];

// ---------------- helpers ----------------
__device__ __forceinline__ void cpa16(void* dst, const void* src, int srcbytes) {
    unsigned d = (unsigned)__cvta_generic_to_shared(dst);
    asm volatile("cp.async.cg.shared.global [%0], [%1], 16, %2;\n"
                 :: "r"(d), "l"(src), "r"(srcbytes));
}
__device__ __forceinline__ void cp_commit() {
    asm volatile("cp.async.commit_group;\n" ::: "memory");
}
template <int NGRP>
__device__ __forceinline__ void cp_wait() {
    asm volatile("cp.async.wait_group %0;\n" :: "n"(NGRP) : "memory");
}

__device__ __forceinline__ void mma_f16(float* c, const unsigned* a, const unsigned* b) {
    asm volatile(
        "mma.sync.aligned.m16n8k16.row.col.f32.f16.f16.f32 "
        "{%0,%1,%2,%3}, {%4,%5,%6,%7}, {%8,%9}, {%0,%1,%2,%3};\n"
        : "+f"(c[0]), "+f"(c[1]), "+f"(c[2]), "+f"(c[3])
        : "r"(a[0]), "r"(a[1]), "r"(a[2]), "r"(a[3]), "r"(b[0]), "r"(b[1]));
}

#define LDSM_X4(r0, r1, r2, r3, a) \
    asm volatile("ldmatrix.sync.aligned.m8n8.x4.shared.b16 {%0,%1,%2,%3}, [%4];" \
                 : "=r"(r0), "=r"(r1), "=r"(r2), "=r"(r3) : "r"(a))
#define LDSM_X4_T(r0, r1, r2, r3, a) \
    asm volatile("ldmatrix.sync.aligned.m8n8.x4.trans.shared.b16 {%0,%1,%2,%3}, [%4];" \
                 : "=r"(r0), "=r"(r1), "=r"(r2), "=r"(r3) : "r"(a))

// ---------------- FP16 tensor-core GEMM ----------------
#define AS_H   (128 * 72)
#define BS_H   (256 * 72)
#define STG_H  (AS_H + BS_H)
#define NST    4

template<int TRANSB>
__device__ __forceinline__ void load_chunk_h(
    __half* As, __half* Bs, const __half* Ab, const __half* Bb,
    int i0, int j0, int M, int Nc, int K, int lda, int ldb,
    int k0, int tid)
{
#pragma unroll
    for (int l = 0; l < 2; ++l) {
        int e = tid + l * 512;
        int row = e >> 3, q = e & 7;
        int gr = i0 + row; if (gr > M - 1) gr = M - 1;
        int gk = k0 + q * 8;
        int rem = K - gk;
        int bytes = rem >= 8 ? 16 : (rem > 0 ? rem * 2 : 0);
        cpa16(As + row * 72 + q * 8, Ab + (size_t)gr * lda + (bytes ? gk : 0), bytes);
    }
    if (TRANSB) {
#pragma unroll
        for (int l = 0; l < 4; ++l) {
            int e = tid + l * 512;
            int row = e >> 3, q = e & 7;
            int gr = j0 + row; if (gr > Nc - 1) gr = Nc - 1;
            int gk = k0 + q * 8;
            int rem = K - gk;
            int bytes = rem >= 8 ? 16 : (rem > 0 ? rem * 2 : 0);
            cpa16(Bs + row * 72 + q * 8, Bb + (size_t)gr * ldb + (bytes ? gk : 0), bytes);
        }
    } else {
#pragma unroll
        for (int l = 0; l < 4; ++l) {
            int e = tid + l * 512;
            int kk = e >> 5;
            int nq = (e & 31) * 8;
            int gk = k0 + kk;
            int bytes = (gk < K) ? 16 : 0;
            cpa16(Bs + kk * 264 + nq, Bb + (size_t)(bytes ? gk : 0) * ldb + j0 + nq, bytes);
        }
    }
}

template<int TRANSB>
__global__ __launch_bounds__(512, 1) void hgemm(
    const __half* __restrict__ A, const __half* __restrict__ Bm,
    const float* __restrict__ bias, void* __restrict__ Cp,
    int M, int Nc, int K, int lda, int ldb, int ldc,
    long long sA, long long sB, long long sC,
    float alpha, int relu, int outHalf,
    int aksub, long long akstr)
{
    extern __shared__ __half smh[];
    const uint32_t sbase = (uint32_t)__cvta_generic_to_shared(smh);

    const __half* Ab = A  + (size_t)blockIdx.z * sA;
    const __half* Bb = Bm + (size_t)blockIdx.z * sB;

    const int tid  = threadIdx.x;
    const int lane = tid & 31;
    const int wid  = tid >> 5;
    const int wr   = (wid & 3) * 32;
    const int wc   = (wid >> 2) * 64;
    const int g    = lane >> 2;
    const int t    = lane & 3;

    const int i0 = blockIdx.y * 128;
    const int j0 = blockIdx.x * 256;

    float acc[2][8][4];
#pragma unroll
    for (int mi = 0; mi < 2; ++mi)
#pragma unroll
        for (int ni = 0; ni < 8; ++ni)
#pragma unroll
            for (int q = 0; q < 4; ++q) acc[mi][ni][q] = 0.f;

    const int nk = (K + 63) / 64;

#pragma unroll
    for (int s = 0; s < 2; ++s) {
        if (s < nk) {
            const __half* AbC = Ab + (aksub ? (long long)((s * 64) / aksub) * akstr : 0);
            load_chunk_h<TRANSB>(smh + s * STG_H, smh + s * STG_H + AS_H, AbC, Bb,
                                 i0, j0, M, Nc, K, lda, ldb, s * 64, tid);
        }
        cp_commit();
    }

    const int a_row = (lane & 15);
    const int a_ko  = 8 * (lane >> 4);
    uint32_t offA[2];
#pragma unroll
    for (int mi = 0; mi < 2; ++mi)
        offA[mi] = (uint32_t)((wr + mi * 16 + a_row) * 72 + a_ko) * 2;

    uint32_t offB[4];
    if (TRANSB) {
        const int bt_row = (lane & 7) + 8 * ((lane >> 4) & 1);
        const int bt_ko  = 8 * ((lane >> 3) & 1);
#pragma unroll
        for (int np = 0; np < 4; ++np)
            offB[np] = (uint32_t)((wc + np * 16 + bt_row) * 72 + bt_ko) * 2;
    } else {
        const int bn_row = (lane & 7) + 8 * ((lane >> 3) & 1);
        const int bn_co  = 8 * (lane >> 4);
#pragma unroll
        for (int np = 0; np < 4; ++np)
            offB[np] = (uint32_t)(bn_row * 264 + wc + np * 16 + bn_co) * 2;
    }

    for (int c = 0; c < nk; ++c) {
        int pf = c + 2;
        if (pf < nk) {
            int st = pf % NST;
            const __half* AbC = Ab + (aksub ? (long long)((pf * 64) / aksub) * akstr : 0);
            load_chunk_h<TRANSB>(smh + st * STG_H, smh + st * STG_H + AS_H, AbC, Bb,
                                 i0, j0, M, Nc, K, lda, ldb, pf * 64, tid);
        }
        cp_commit();
        cp_wait<2>();
        __syncthreads();

        const uint32_t aoff = sbase + (uint32_t)((c % NST) * STG_H) * 2;
        const uint32_t boff = aoff + AS_H * 2;

#pragma unroll
        for (int k16 = 0; k16 < 4; ++k16) {
            unsigned af[2][4];
#pragma unroll
            for (int mi = 0; mi < 2; ++mi) {
                uint32_t ad = aoff + offA[mi] + (uint32_t)(k16 * 32);
                LDSM_X4(af[mi][0], af[mi][1], af[mi][2], af[mi][3], ad);
            }
            unsigned bf[8][2];
            if (TRANSB) {
#pragma unroll
                for (int np = 0; np < 4; ++np) {
                    uint32_t bd = boff + offB[np] + (uint32_t)(k16 * 32);
                    LDSM_X4(bf[2 * np][0], bf[2 * np][1],
                            bf[2 * np + 1][0], bf[2 * np + 1][1], bd);
                }
            } else {
#pragma unroll
                for (int np = 0; np < 4; ++np) {
                    uint32_t bd = boff + offB[np] + (uint32_t)(k16 * 16 * 264 * 2);
                    LDSM_X4_T(bf[2 * np][0], bf[2 * np][1],
                              bf[2 * np + 1][0], bf[2 * np + 1][1], bd);
                }
            }
#pragma unroll
            for (int mi = 0; mi < 2; ++mi)
#pragma unroll
                for (int ni = 0; ni < 8; ++ni)
                    mma_f16(acc[mi][ni], af[mi], bf[ni]);
        }
    }
    cp_wait<0>();

    // epilogue
    float* Cf = (float*)Cp + (size_t)blockIdx.z * sC;
    __half* Ch = (__half*)Cp + (size_t)blockIdx.z * sC;
#pragma unroll
    for (int mi = 0; mi < 2; ++mi) {
        int r0 = i0 + wr + mi * 16 + g;
#pragma unroll
        for (int ni = 0; ni < 8; ++ni) {
            int c0 = j0 + wc + ni * 8 + 2 * t;
            float b0v = 0.f, b1v = 0.f;
            if (bias && c0 < Nc) { b0v = bias[c0]; b1v = (c0 + 1 < Nc) ? bias[c0 + 1] : 0.f; }
            float v00 = alpha * acc[mi][ni][0] + b0v;
            float v01 = alpha * acc[mi][ni][1] + b1v;
            float v10 = alpha * acc[mi][ni][2] + b0v;
            float v11 = alpha * acc[mi][ni][3] + b1v;
            if (relu) {
                v00 = fmaxf(v00, 0.f); v01 = fmaxf(v01, 0.f);
                v10 = fmaxf(v10, 0.f); v11 = fmaxf(v11, 0.f);
            }
            if (outHalf) {
                if (r0 < M && c0 < Nc)
                    *(__half2*)&Ch[(size_t)r0 * ldc + c0] = __floats2half2_rn(v00, v01);
                if (r0 + 8 < M && c0 < Nc)
                    *(__half2*)&Ch[(size_t)(r0 + 8) * ldc + c0] = __floats2half2_rn(v10, v11);
            } else {
                if (r0 < M) {
                    if (c0 < Nc)     Cf[(size_t)r0 * ldc + c0]     = v00;
                    if (c0 + 1 < Nc) Cf[(size_t)r0 * ldc + c0 + 1] = v01;
                }
                if (r0 + 8 < M) {
                    if (c0 < Nc)     Cf[(size_t)(r0 + 8) * ldc + c0]     = v10;
                    if (c0 + 1 < Nc) Cf[(size_t)(r0 + 8) * ldc + c0 + 1] = v11;
                }
            }
        }
    }
}

// ---------------- small NN GEMM for adj powers (fp16 in, fp32 acc) ----------------
// C[N_ x SCLD] = A[N_ x SCLD(K=N_)] @ B[N_ x SCLD], 32x32 tiles, grid (7,7), block (32,8)
__global__ void small_nn(const __half* __restrict__ A, const __half* __restrict__ Bm,
                         __half* __restrict__ C) {
    __shared__ __half As[32][40];
    __shared__ __half Bs[32][40];
    int tx = threadIdx.x, ty = threadIdx.y;
    int tid = ty * 32 + tx;
    int i0 = blockIdx.y * 32, j0 = blockIdx.x * 32;
    float acc[4] = {0.f, 0.f, 0.f, 0.f};
    for (int k0 = 0; k0 < N_; k0 += 32) {
#pragma unroll
        for (int l = 0; l < 4; ++l) {
            int e = tid + l * 256;
            int r = e >> 5, kk = e & 31;
            As[r][kk] = (i0 + r < N_ && k0 + kk < N_)
                        ? A[(size_t)(i0 + r) * SCLD + k0 + kk] : __float2half(0.f);
            Bs[r][kk] = (k0 + r < N_ && j0 + kk < N_)
                        ? Bm[(size_t)(k0 + r) * SCLD + j0 + kk] : __float2half(0.f);
        }
        __syncthreads();
#pragma unroll
        for (int kk = 0; kk < 32; ++kk) {
            float bv = __half2float(Bs[kk][tx]);
#pragma unroll
            for (int r = 0; r < 4; ++r)
                acc[r] += __half2float(As[ty * 4 + r][kk]) * bv;
        }
        __syncthreads();
    }
#pragma unroll
    for (int r = 0; r < 4; ++r) {
        int i = i0 + ty * 4 + r;
        if (i < N_ && j0 + tx < SCLD)
            C[(size_t)i * SCLD + j0 + tx] = __float2half(acc[r]);
    }
}

// ---------------- elementwise kernels ----------------

#define PR0 (QKVLD * D_)
#define PR1 (PR0 + D_ * D_)
#define PR2 (PR1 + D_ * D_)
#define PR3 (PR2 + D_ * D_)
#define PR4 (PR3 + 512 * KC_)
#define PR5 (PR4 + 512)
#define PR6 (PR5 + N_ * SCLD)
__global__ void prep_all(const float* __restrict__ wq, const float* __restrict__ wo,
                         const float* __restrict__ w1, const float* __restrict__ w2,
                         const float* __restrict__ Wu, const float* __restrict__ Wc,
                         const float* __restrict__ bu, const float* __restrict__ bc,
                         const float* __restrict__ adj) {
    int i = blockIdx.x * 256 + threadIdx.x;
    if (i < PR0) {
        g_wqh[i] = __float2half(wq[i]);
    } else if (i < PR1) {
        int j = i - PR0; g_woh[j] = __float2half(wo[j]);
    } else if (i < PR2) {
        int j = i - PR1; g_w1h[j] = __float2half(w1[j]);
    } else if (i < PR3) {
        int j = i - PR2; g_w2h[j] = __float2half(w2[j]);
    } else if (i < PR4) {
        int j = i - PR3;
        int row = j / KC_, k = j % KC_;
        float v = (row < 256) ? Wu[(size_t)row * KC_ + k] : Wc[(size_t)(row - 256) * KC_ + k];
        g_wuch[j] = __float2half(v);
    } else if (i < PR5) {
        int j = i - PR4;
        g_buc[j] = (j < 256) ? bu[j] : bc[j - 256];
    } else if (i < PR6) {
        int j = i - PR5;
        int r = j / SCLD, c = j % SCLD;
        g_adjh[j] = __float2half((c < N_) ? adj[(size_t)r * N_ + c] : 0.f);
    }
}

// merged transpose, vectorized writer (4 consecutive c per thread)
__global__ void trans_hx(const float* __restrict__ h, const float* __restrict__ x,
                         const float* __restrict__ embed, const float* __restrict__ mlt) {
    int b = blockIdx.z;
    int n0 = blockIdx.x * 32;
    __shared__ float tile[32][33];
    int tx = threadIdx.x, ty = threadIdx.y;
    int tid = ty * 32 + tx;
    if (blockIdx.y < 8) {
        int c0 = blockIdx.y * 32;
#pragma unroll
        for (int l = 0; l < 4; ++l) {
            int c = c0 + ty + l * 8;
            int n = n0 + tx;
            tile[ty + l * 8][tx] = (n < N_) ? h[((size_t)b * D_ + c) * N_ + n] : 0.f;
        }
        __syncthreads();
        int nl = tid >> 3, cq = (tid & 7) * 4;
        int n = n0 + nl;
        if (n < N_) {
            int c = c0 + cq;
            float m = mlt[(size_t)b * N_ + n];
            float4 e = *(const float4*)&embed[(size_t)n * D_ + c];
            float v0 = tile[cq + 0][nl] + e.x * m;
            float v1 = tile[cq + 1][nl] + e.y * m;
            float v2 = tile[cq + 2][nl] + e.z * m;
            float v3 = tile[cq + 3][nl] + e.w * m;
            size_t idx = ((size_t)b * N_ + n) * D_ + c;
            *(float4*)&g_s[idx] = make_float4(v0, v1, v2, v3);
            *(__half2*)&g_sh[idx]     = __floats2half2_rn(v0, v1);
            *(__half2*)&g_sh[idx + 2] = __floats2half2_rn(v2, v3);
        }
    } else {
        int c0 = (blockIdx.y - 8) * 32;
#pragma unroll
        for (int l = 0; l < 4; ++l) {
            int c = c0 + ty + l * 8;
            int n = n0 + tx;
            tile[ty + l * 8][tx] = (n < N_) ? x[((size_t)b * DIN_ + c) * N_ + n] : 0.f;
        }
        __syncthreads();
        int nl = tid >> 3, cq = (tid & 7) * 4;
        int n = n0 + nl;
        if (n < N_) {
            size_t idx = ((size_t)n * B_ + b) * CXG_ + c0 + cq;
            *(__half2*)&g_zh[idx] =
                __floats2half2_rn(tile[cq + 0][nl], tile[cq + 1][nl]);
            *(__half2*)&g_zh[idx + 2] =
                __floats2half2_rn(tile[cq + 2][nl], tile[cq + 3][nl]);
        }
    }
}

// in-place softmax on fp16 scores, 16 rows per block (512 threads)
__global__ void softmax_rows(__half* __restrict__ sch) {
    int row = blockIdx.x * 16 + threadIdx.y;
    __half* p = sch + (size_t)row * SCLD;
    int lane = threadIdx.x;
    float ev[7];
    float mx = -1e30f;
    int cnt = 0;
    for (int j = lane; j < N_; j += 32) {
        float v = __half2float(p[j]);
        ev[cnt++] = v;
        mx = fmaxf(mx, v);
    }
#pragma unroll
    for (int o = 16; o > 0; o >>= 1) mx = fmaxf(mx, __shfl_xor_sync(0xffffffffu, mx, o));
    float sum = 0.f;
    for (int i = 0; i < cnt; ++i) { ev[i] = expf(ev[i] - mx); sum += ev[i]; }
#pragma unroll
    for (int o = 16; o > 0; o >>= 1) sum += __shfl_xor_sync(0xffffffffu, sum, o);
    float inv = 1.f / sum;
    cnt = 0;
    for (int j = lane; j < N_; j += 32) p[j] = __float2half(ev[cnt++] * inv);
}

__device__ __forceinline__ float2 ln_stats(float v, int c, float* red2) {
    float s = v, q = v * v;
#pragma unroll
    for (int o = 16; o > 0; o >>= 1) {
        s += __shfl_xor_sync(0xffffffffu, s, o);
        q += __shfl_xor_sync(0xffffffffu, q, o);
    }
    if ((c & 31) == 0) { red2[(c >> 5) * 2] = s; red2[(c >> 5) * 2 + 1] = q; }
    __syncthreads();
    float ts = 0.f, tq = 0.f;
#pragma unroll
    for (int w = 0; w < 8; ++w) { ts += red2[w * 2]; tq += red2[w * 2 + 1]; }
    float mu = ts * (1.f / 256.f);
    float var = tq * (1.f / 256.f) - mu * mu;
    return make_float2(mu, rsqrtf(var + 1e-5f));
}

__global__ void add_ln(const float* __restrict__ a, const float* __restrict__ bsrc,
                       const float* __restrict__ w, const float* __restrict__ bb,
                       float* __restrict__ outf, __half* __restrict__ outh) {
    int r = blockIdx.x, c = threadIdx.x;
    size_t idx = (size_t)r * D_ + c;
    float v = a[idx] + bsrc[idx];
    __shared__ float red2[16];
    float2 st = ln_stats(v, c, red2);
    float o = (v - st.x) * st.y * w[c] + bb[c];
    outf[idx] = o;
    outh[idx] = __float2half(o);
}

__global__ void ln2_make_h(const float* __restrict__ a, const float* __restrict__ bsrc,
                           const float* __restrict__ w, const float* __restrict__ bb,
                           const float* __restrict__ embed, const float* __restrict__ mlt,
                           const float* __restrict__ dt, const int* __restrict__ step) {
    int r = blockIdx.x, c = threadIdx.x;
    int b = r / N_, n = r % N_;
    size_t idx = (size_t)r * D_ + c;
    float v = a[idx] + bsrc[idx];
    __shared__ float red2[16];
    float2 st = ln_stats(v, c, red2);
    float s3v = (v - st.x) * st.y * w[c] + bb[c];

    float hv = g_s[idx] - embed[(size_t)n * D_ + c] * mlt[(size_t)b * N_ + n];
    float hn;
    if (*step != 0) {
        float d = dt[b];
        hn = sqrtf(1.f - d) * hv - sqrtf(d) * tanhf(s3v);
    } else {
        hn = hv;
    }
    g_hn[idx] = hn;
    g_zh[((size_t)n * B_ + b) * CXG_ + DIN_ + c] = __float2half(hn);
}

__global__ void final_combine(float* __restrict__ outp) {
    int b = blockIdx.z;
    int o0 = blockIdx.y * 32, n0 = blockIdx.x * 32;
    __shared__ float tbuf[32][33];
    int tx = threadIdx.x, ty = threadIdx.y;
#pragma unroll
    for (int s4 = 0; s4 < 4; ++s4) {
        int nl = ty + s4 * 8;
        int n = n0 + nl;
        float val = 0.f;
        if (n < N_) {
            size_t rp = (size_t)n * B_ + b;
            float gu = g_guc[rp * 512 + o0 + tx];
            float gc = g_guc[rp * 512 + 256 + o0 + tx];
            float uu = 1.f / (1.f + expf(-gu));
            float cc = tanhf(gc);
            val = uu * g_hn[((size_t)b * N_ + n) * D_ + o0 + tx] + (1.f - uu) * cc;
        }
        tbuf[nl][tx] = val;
    }
    __syncthreads();
#pragma unroll
    for (int s4 = 0; s4 < 4; ++s4) {
        int ol = ty + s4 * 8;
        int n = n0 + tx;
        if (n < N_)
            outp[((size_t)(b * D_ + o0 + ol)) * N_ + n] = tbuf[tx][ol];
    }
}

// ---------------- launcher ----------------
extern "C" void kernel_launch(void* const* d_in, const int* in_sizes, int n_in,
                              void* d_out, int out_size) {
    const float* x          = (const float*)d_in[0];
    const float* delta_t    = (const float*)d_in[1];
    const float* h          = (const float*)d_in[2];
    const float* adj        = (const float*)d_in[3];
    const float* mlt        = (const float*)d_in[5];
    const int*   step       = (const int*)d_in[7];
    const float* embed      = (const float*)d_in[8];
    const float* in_proj_w  = (const float*)d_in[9];
    const float* in_proj_b  = (const float*)d_in[10];
    const float* out_proj_w = (const float*)d_in[11];
    const float* out_proj_b = (const float*)d_in[12];
    const float* ln1_w      = (const float*)d_in[13];
    const float* ln1_b      = (const float*)d_in[14];
    const float* ln2_w      = (const float*)d_in[15];
    const float* ln2_b      = (const float*)d_in[16];
    const float* ffn_w1     = (const float*)d_in[17];
    const float* ffn_b1     = (const float*)d_in[18];
    const float* ffn_w2     = (const float*)d_in[19];
    const float* ffn_b2     = (const float*)d_in[20];
    const float* W_u        = (const float*)d_in[21];
    const float* b_u        = (const float*)d_in[22];
    const float* W_c        = (const float*)d_in[23];
    const float* b_c        = (const float*)d_in[24];
    float* outp = (float*)d_out;

    void *vp;
    cudaGetSymbolAddress(&vp, g_s);    float*  ps   = (float*)vp;
    cudaGetSymbolAddress(&vp, g_sh);   __half* psh  = (__half*)vp;
    cudaGetSymbolAddress(&vp, g_qkvh); __half* pqh  = (__half*)vp;
    cudaGetSymbolAddress(&vp, g_sch);  __half* psch = (__half*)vp;
    cudaGetSymbolAddress(&vp, g_adjh); __half* padh = (__half*)vp;
    cudaGetSymbolAddress(&vp, g_oh);   __half* poh  = (__half*)vp;
    cudaGetSymbolAddress(&vp, g_f1);   float*  pf1  = (float*)vp;
    cudaGetSymbolAddress(&vp, g_s2);   float*  ps2  = (float*)vp;
    cudaGetSymbolAddress(&vp, g_s2h);  __half* ps2h = (__half*)vp;
    cudaGetSymbolAddress(&vp, g_poh);  __half* ppoh = (__half*)vp;
    cudaGetSymbolAddress(&vp, g_zh);   __half* pzh  = (__half*)vp;
    cudaGetSymbolAddress(&vp, g_guc);  float*  pguc = (float*)vp;
    cudaGetSymbolAddress(&vp, g_wuch); __half* pwuh = (__half*)vp;
    cudaGetSymbolAddress(&vp, g_buc);  float*  pbuc = (float*)vp;
    cudaGetSymbolAddress(&vp, g_wqh);  __half* pwq  = (__half*)vp;
    cudaGetSymbolAddress(&vp, g_woh);  __half* pwo  = (__half*)vp;
    cudaGetSymbolAddress(&vp, g_w1h);  __half* pw1  = (__half*)vp;
    cudaGetSymbolAddress(&vp, g_w2h);  __half* pw2  = (__half*)vp;

    __half* padj2 = padh + (size_t)N_ * SCLD;
    __half* padj3 = padh + 2 * (size_t)N_ * SCLD;

    static const int SMH = NST * STG_H * 2;   // 221184 bytes
    cudaFuncSetAttribute(hgemm<0>, cudaFuncAttributeMaxDynamicSharedMemorySize, SMH);
    cudaFuncSetAttribute(hgemm<1>, cudaFuncAttributeMaxDynamicSharedMemorySize, SMH);

    // 0. merged prep (adj -> fp16 slot 0)
    prep_all<<<(PR6 + 255) / 256, 256>>>(in_proj_w, out_proj_w, ffn_w1, ffn_w2,
                                         W_u, W_c, b_u, b_c, adj);

    // 0b. adj powers via small-tile NN kernel
    small_nn<<<dim3(7, 7), dim3(32, 8)>>>(padh, padh, padj2);
    small_nn<<<dim3(7, 7), dim3(32, 8)>>>(padj2, padh, padj3);

    // 1. transformer input + Z0 x-part (merged, vectorized)
    trans_hx<<<dim3(7, 10, B_), dim3(32, 8)>>>(h, x, embed, mlt);

    // 2. QKV -> fp16
    hgemm<1><<<dim3(3, 414, 1), 512, SMH>>>(psh, pwq, in_proj_b, pqh,
        NB_, QKVLD, 256, 256, 256, QKVLD, 0, 0, 0, 1.f, 0, 1, 0, 0);

    // 3. scores: per-batch Q @ K^T / 16 -> fp16
    hgemm<1><<<dim3(1, 2, B_), 512, SMH>>>(pqh, pqh + 256, nullptr, psch,
        N_, N_, 256, QKVLD, QKVLD, SCLD,
        (long long)N_ * QKVLD, (long long)N_ * QKVLD, (long long)N_ * SCLD,
        1.f / 16.f, 0, 1, 0, 0);

    // 4. softmax in-place (16 rows/block)
    softmax_rows<<<NB_ / 16, dim3(32, 16)>>>(psch);

    // 5. attn @ V (NN) -> fp16
    hgemm<0><<<dim3(1, 2, B_), 512, SMH>>>(psch, pqh + 512, nullptr, poh,
        N_, 256, N_, SCLD, QKVLD, 256,
        (long long)N_ * SCLD, (long long)N_ * QKVLD, (long long)N_ * 256,
        1.f, 0, 1, 0, 0);

    // 6. out projection -> fp32
    hgemm<1><<<dim3(1, 414, 1), 512, SMH>>>(poh, pwo, out_proj_b, pf1,
        NB_, 256, 256, 256, 256, 256, 0, 0, 0, 1.f, 0, 0, 0, 0);

    // 7. LN1
    add_ln<<<NB_, 256>>>(ps, pf1, ln1_w, ln1_b, ps2, ps2h);

    // 8. FFN
    hgemm<1><<<dim3(1, 414, 1), 512, SMH>>>(ps2h, pw1, ffn_b1, ppoh,
        NB_, 256, 256, 256, 256, 256, 0, 0, 0, 1.f, 1, 1, 0, 0);
    hgemm<1><<<dim3(1, 414, 1), 512, SMH>>>(ppoh, pw2, ffn_b2, pf1,
        NB_, 256, 256, 256, 256, 256, 0, 0, 0, 1.f, 0, 0, 0, 0);

    // 9+10. LN2 + h update + Z0 h-part
    ln2_make_h<<<NB_, 256>>>(ps2, pf1, ln2_w, ln2_b, embed, mlt, delta_t, step);

    // 11. diffusion: Z_k = adj^k @ Z0, ONE batched launch over k=1..3
    hgemm<0><<<dim3(ZROW / 256, 2, 3), 512, SMH>>>(padh, pzh, nullptr, pzh + ZK,
        N_, ZROW, N_, SCLD, ZROW, ZROW,
        (long long)N_ * SCLD, 0, (long long)ZK,
        1.f, 0, 1, 0, 0);

    // 12. fused gates (blocked-K z) -> fp32
    hgemm<1><<<dim3(2, 414, 1), 512, SMH>>>(pzh, pwuh, pbuc, pguc,
        NB_, 512, KC_, CXG_, KC_, 512, 0, 0, 0, 1.f, 0, 0,
        CXG_, (long long)ZK - CXG_);

    // 13. gated combine + transpose
    final_combine<<<dim3(7, 8, B_), dim3(32, 8)>>>(outp);
}